// round 10
// baseline (speedup 1.0000x reference)
#include <cuda_runtime.h>
#include <cuda_fp16.h>
#include <stdint.h>
#include <math.h>

// Problem constants
#define Bq    8
#define Cq    512
#define Nq    1024
#define HEADS 8
#define HD    64
#define GROUPS 32
#define CPG   16
#define EPS   1e-5f
#define LOG2E 1.4426950408889634f
#define QSC   0.18033688011112042f   // 0.125 * LOG2E
#define ONE2  0x3C003C00u            // fp16 {1.0, 1.0}
#define SC2M8 0x1C001C00u            // fp16 {2^-8, 2^-8}: exact fixed-max shift

// Scratch (device globals — no cudaMalloc allowed)
__device__ __half g_hnT [Bq * Nq * Cq];          // [b][n][c]
__device__ __half g_q   [Bq * HEADS * Nq * HD];  // [b][h][n][c], scale folded
__device__ __half g_k   [Bq * HEADS * Nq * HD];  // [b][h][n][c]
__device__ __half g_v   [Bq * HEADS * HD * Nq];  // [b][h][c][n]
__device__ __half g_attT[Bq * Nq * Cq];          // [b][n][c]
__device__ __half g_wq  [3 * Cq * Cq];
__device__ __half g_wp  [Cq * Cq];

// ---------------------------------------------------------------------------
// helpers
// ---------------------------------------------------------------------------
__device__ __forceinline__ uint32_t ex2h2(uint32_t x) {
    uint32_t r; asm("ex2.approx.f16x2 %0, %1;" : "=r"(r) : "r"(x)); return r;
}
__device__ __forceinline__ uint32_t mulh2(uint32_t a, uint32_t b) {
    uint32_t r; asm("mul.f16x2 %0, %1, %2;" : "=r"(r) : "r"(a), "r"(b)); return r;
}
// pack: lo half <- a, hi half <- b
__device__ __forceinline__ uint32_t packh2(float a, float b) {
    uint32_t r;
    asm("cvt.rn.satfinite.f16x2.f32 %0, %1, %2;" : "=r"(r) : "f"(b), "f"(a));
    return r;
}
__device__ __forceinline__ void mma_f16(float c[4],
                                        uint32_t a0, uint32_t a1, uint32_t a2, uint32_t a3,
                                        uint32_t b0, uint32_t b1) {
    asm volatile(
        "mma.sync.aligned.m16n8k16.row.col.f32.f16.f16.f32 "
        "{%0,%1,%2,%3}, {%4,%5,%6,%7}, {%8,%9}, {%0,%1,%2,%3};"
        : "+f"(c[0]), "+f"(c[1]), "+f"(c[2]), "+f"(c[3])
        : "r"(a0), "r"(a1), "r"(a2), "r"(a3), "r"(b0), "r"(b1));
}
// fp16 accumulator variant: C/D are 2x f16x2 regs
__device__ __forceinline__ void mma_f16acc(uint32_t c[2],
                                           uint32_t a0, uint32_t a1, uint32_t a2, uint32_t a3,
                                           uint32_t b0, uint32_t b1) {
    asm volatile(
        "mma.sync.aligned.m16n8k16.row.col.f16.f16.f16.f16 "
        "{%0,%1}, {%2,%3,%4,%5}, {%6,%7}, {%0,%1};"
        : "+r"(c[0]), "+r"(c[1])
        : "r"(a0), "r"(a1), "r"(a2), "r"(a3), "r"(b0), "r"(b1));
}
__device__ __forceinline__ void ldmx4(uint32_t& r0, uint32_t& r1, uint32_t& r2,
                                      uint32_t& r3, uint32_t addr) {
    asm volatile("ldmatrix.sync.aligned.m8n8.x4.shared.b16 {%0,%1,%2,%3}, [%4];"
                 : "=r"(r0), "=r"(r1), "=r"(r2), "=r"(r3) : "r"(addr));
}
__device__ __forceinline__ uint32_t smem_u32(const void* p) {
    return (uint32_t)__cvta_generic_to_shared(p);
}
__device__ __forceinline__ void cp16s(uint32_t* dst_smem, const void* src) {
    uint32_t d = smem_u32(dst_smem);
    asm volatile("cp.async.cg.shared.global [%0], [%1], 16;" :: "r"(d), "l"(src));
}
__device__ __forceinline__ void cp_commit() {
    asm volatile("cp.async.commit_group;");
}
template <int N>
__device__ __forceinline__ void cp_wait() {
    asm volatile("cp.async.wait_group %0;" :: "n"(N));
}

// ---------------------------------------------------------------------------
// Kernel 0: both weights f32 -> fp16, one launch
// ---------------------------------------------------------------------------
__global__ void cvt_f16_kernel(const float* __restrict__ s1, __half* __restrict__ d1, int n1,
                               const float* __restrict__ s2, __half* __restrict__ d2, int n2) {
    int i = blockIdx.x * 256 + threadIdx.x;
    const float* s; __half* d;
    if (i < n1) { s = s1; d = d1; }
    else if (i < n1 + n2) { s = s2; d = d2; i -= n1; }
    else return;
    float4 v = ((const float4*)s)[i];
    uint2 u;
    u.x = packh2(v.x, v.y);
    u.y = packh2(v.z, v.w);
    ((uint2*)d)[i] = u;
}

// ---------------------------------------------------------------------------
// Kernel 1: GroupNorm -> transposed fp16 output hnT[b][n][c]
// ---------------------------------------------------------------------------
__global__ void gn_kernel(const float* __restrict__ x,
                          const float* __restrict__ gamma,
                          const float* __restrict__ beta,
                          __half* __restrict__ hnT) {
    __shared__ float rs[256], rs2[256];
    __shared__ float ts[256][17];

    int bg = blockIdx.x;
    int b = bg >> 5, g = bg & 31;
    const size_t base = ((size_t)b * Cq + (size_t)g * CPG) * Nq;
    const float* xp = x + base;
    const int tid = threadIdx.x;

    float s = 0.f, s2 = 0.f;
    for (int i = tid; i < CPG * Nq; i += 256) {
        float v = xp[i];
        s += v; s2 += v * v;
    }
    rs[tid] = s; rs2[tid] = s2;
    __syncthreads();
    for (int st = 128; st > 0; st >>= 1) {
        if (tid < st) { rs[tid] += rs[tid + st]; rs2[tid] += rs2[tid + st]; }
        __syncthreads();
    }
    float mu   = rs[0]  * (1.f / 16384.f);
    float var  = rs2[0] * (1.f / 16384.f) - mu * mu;
    float rinv = rsqrtf(var + EPS);

    const int cl = tid >> 4;
    const int sg = tid & 15;
    const int cg = g * CPG + cl;
    const float ga = gamma[cg] * rinv;
    const float be = beta[cg] - mu * ga;

    __half* hb = hnT + (size_t)b * Nq * Cq;

    for (int chunk = 0; chunk < 4; chunk++) {
        int n0 = chunk * 256;
        const float* src = xp + (size_t)cl * Nq + n0 + sg * 16;
        #pragma unroll
        for (int q = 0; q < 4; q++) {
            float4 v = *(const float4*)(src + q * 4);
            int nl = sg * 16 + q * 4;
            ts[nl + 0][cl] = v.x * ga + be;
            ts[nl + 1][cl] = v.y * ga + be;
            ts[nl + 2][cl] = v.z * ga + be;
            ts[nl + 3][cl] = v.w * ga + be;
        }
        __syncthreads();
        #pragma unroll
        for (int rep = 0; rep < 4; rep++) {
            int nl = (tid >> 2) + rep * 64;
            int j4 = (tid & 3) * 4;
            uint2 u;
            u.x = packh2(ts[nl][j4],     ts[nl][j4 + 1]);
            u.y = packh2(ts[nl][j4 + 2], ts[nl][j4 + 3]);
            *(uint2*)&hb[(size_t)(n0 + nl) * Cq + g * CPG + j4] = u;
        }
        __syncthreads();
    }
}

// ---------------------------------------------------------------------------
// Kernel 2/4: fp16 GEMM, BM=128 BN=64 BK=32, 256 threads (8 warps: 4Mx2N,
// warp tile 32x32). 3-stage cp.async. 3 CTAs/SM via launch_bounds.
// ---------------------------------------------------------------------------
#define GA_STG  2560      // A stage u32 (128*20)
#define GB_STG  1280      // B stage u32 (64*20)
#define GB_OFF  7680      // 3*GA_STG
#define G_SMEM_BYTES ((3 * GA_STG + 3 * GB_STG) * 4)   // 46080

template <int MODE>
__global__ __launch_bounds__(256, 3)
void gemm_f16(const __half* __restrict__ W, const __half* __restrict__ BT,
              const float* __restrict__ bias, const float* __restrict__ resid,
              float* __restrict__ Y,
              __half* __restrict__ gq, __half* __restrict__ gk,
              __half* __restrict__ gv,
              int M, int K, int N) {
    extern __shared__ uint32_t smg[];
    uint32_t* As = smg;
    uint32_t* Bs = smg + GB_OFF;

    const int b  = blockIdx.z;
    const int m0 = blockIdx.y * 128, n0 = blockIdx.x * 64;
    const __half* BTb = BT + (size_t)b * Nq * Cq;

    const int tid  = threadIdx.x;
    const int lane = tid & 31, warp = tid >> 5;
    const int g = lane >> 2, t = lane & 3;
    const int wm = (warp >> 1) * 32;
    const int wn = (warp & 1) * 32;

    const int a_row  = lane & 15;
    const int a_coff = ((lane >> 4) & 1) * 4;
    const int b_row  = (lane & 7) + ((lane >> 4) & 1) * 8;
    const int b_coff = ((lane >> 3) & 1) * 4;

    float acc[2][4][4];
    #pragma unroll
    for (int i = 0; i < 2; i++)
        #pragma unroll
        for (int j = 0; j < 4; j++)
            #pragma unroll
            for (int k = 0; k < 4; k++) acc[i][j][k] = 0.f;

    const int NIT = K / 32;

    auto load_stage = [&](int stage, int k0) {
        uint32_t* as = As + stage * GA_STG;
        uint32_t* bs = Bs + stage * GB_STG;
        #pragma unroll
        for (int r = 0; r < 2; r++) {
            int idx = tid + r * 256;
            int row = idx >> 2, ch = idx & 3;
            cp16s(as + row * 20 + ch * 4, W + (size_t)(m0 + row) * K + k0 + ch * 8);
        }
        {
            int row = tid >> 2, ch = tid & 3;
            cp16s(bs + row * 20 + ch * 4, BTb + (size_t)(n0 + row) * K + k0 + ch * 8);
        }
    };

    load_stage(0, 0);  cp_commit();
    load_stage(1, 32); cp_commit();

    for (int it = 0; it < NIT; it++) {
        cp_wait<1>();
        __syncthreads();
        if (it + 2 < NIT) load_stage((it + 2) % 3, (it + 2) * 32);
        cp_commit();

        uint32_t asb = smem_u32(As + (it % 3) * GA_STG);
        uint32_t bsb = smem_u32(Bs + (it % 3) * GB_STG);
        #pragma unroll
        for (int s = 0; s < 2; s++) {
            uint32_t af[2][4];
            #pragma unroll
            for (int mt = 0; mt < 2; mt++)
                ldmx4(af[mt][0], af[mt][1], af[mt][2], af[mt][3],
                      asb + ((wm + mt * 16 + a_row) * 20 + 8 * s + a_coff) * 4);
            uint32_t bb[8];
            #pragma unroll
            for (int p = 0; p < 2; p++)
                ldmx4(bb[4 * p], bb[4 * p + 1], bb[4 * p + 2], bb[4 * p + 3],
                      bsb + ((wn + p * 16 + b_row) * 20 + 8 * s + b_coff) * 4);
            #pragma unroll
            for (int nt = 0; nt < 4; nt++) {
                uint32_t b0 = bb[4 * (nt >> 1) + 2 * (nt & 1)];
                uint32_t b1 = bb[4 * (nt >> 1) + 2 * (nt & 1) + 1];
                mma_f16(acc[0][nt], af[0][0], af[0][1], af[0][2], af[0][3], b0, b1);
                mma_f16(acc[1][nt], af[1][0], af[1][1], af[1][2], af[1][3], b0, b1);
            }
        }
    }

    if (MODE == 0) {
        const int sel = m0 >> 9;
        #pragma unroll
        for (int mt = 0; mt < 2; mt++) {
            int m  = m0 + wm + mt * 16 + g;
            float bv0 = bias[m], bv1 = bias[m + 8];
            int hh = (m >> 6) & 7;
            int c0 = m & 63;
            #pragma unroll
            for (int nt = 0; nt < 4; nt++) {
                int n = n0 + wn + nt * 8 + 2 * t;
                float v00 = acc[mt][nt][0] + bv0, v01 = acc[mt][nt][1] + bv0;
                float v10 = acc[mt][nt][2] + bv1, v11 = acc[mt][nt][3] + bv1;
                if (sel == 0) {
                    size_t qb = ((size_t)(b * 8 + hh) * 1024);
                    gq[(qb + n) * 64 + c0]         = __float2half_rn(v00 * QSC);
                    gq[(qb + n + 1) * 64 + c0]     = __float2half_rn(v01 * QSC);
                    gq[(qb + n) * 64 + c0 + 8]     = __float2half_rn(v10 * QSC);
                    gq[(qb + n + 1) * 64 + c0 + 8] = __float2half_rn(v11 * QSC);
                } else if (sel == 1) {
                    size_t kb = ((size_t)(b * 8 + hh) * 1024);
                    gk[(kb + n) * 64 + c0]         = __float2half_rn(v00);
                    gk[(kb + n + 1) * 64 + c0]     = __float2half_rn(v01);
                    gk[(kb + n) * 64 + c0 + 8]     = __float2half_rn(v10);
                    gk[(kb + n + 1) * 64 + c0 + 8] = __float2half_rn(v11);
                } else {
                    size_t vb = ((size_t)(b * 8 + hh) * 64);
                    *(uint32_t*)&gv[(vb + c0) * 1024 + n]     = packh2(v00, v01);
                    *(uint32_t*)&gv[(vb + c0 + 8) * 1024 + n] = packh2(v10, v11);
                }
            }
        }
    } else {
        float*       Yb = Y + (size_t)b * Cq * Nq;
        const float* Rb = resid + (size_t)b * Cq * Nq;
        #pragma unroll
        for (int mt = 0; mt < 2; mt++) {
            int r0 = m0 + wm + mt * 16 + g;
            int r1 = r0 + 8;
            float bv0 = bias[r0], bv1 = bias[r1];
            #pragma unroll
            for (int nt = 0; nt < 4; nt++) {
                int cc = n0 + wn + nt * 8 + 2 * t;
                float2 q0 = *(const float2*)&Rb[(size_t)r0 * N + cc];
                float2 q1 = *(const float2*)&Rb[(size_t)r1 * N + cc];
                float2 v0 = make_float2(acc[mt][nt][0] + bv0 + q0.x,
                                        acc[mt][nt][1] + bv0 + q0.y);
                float2 v1 = make_float2(acc[mt][nt][2] + bv1 + q1.x,
                                        acc[mt][nt][3] + bv1 + q1.y);
                *(float2*)&Yb[(size_t)r0 * N + cc] = v0;
                *(float2*)&Yb[(size_t)r1 * N + cc] = v1;
            }
        }
    }
}

// ---------------------------------------------------------------------------
// Kernel 3: fp16 flash attention, fixed-max softmax, fp16 S *and* O/l
// accumulators. 4 CTAs/SM via launch_bounds (64-reg cap).
// ---------------------------------------------------------------------------
#define AK_OFF  4608
#define AK_STG  2304          // 64*36
#define AV_OFF  9216
#define AV_STG  2304
#define ATTN_SMEM_BYTES (13824 * 4)

__global__ __launch_bounds__(256, 4)
void attn_f16() {
    extern __shared__ uint32_t sma[];
    uint32_t* Qs = sma;
    uint32_t* Ks = sma + AK_OFF;
    uint32_t* Vs = sma + AV_OFF;

    const int qt = blockIdx.x, h = blockIdx.y, b = blockIdx.z;
    const __half* Qp = g_q + ((size_t)(b * 8 + h) * 1024 + qt * 128) * 64;
    const __half* Kp = g_k + ((size_t)(b * 8 + h) * 1024) * 64;
    const __half* Vp = g_v + ((size_t)(b * 8 + h) * 64) * 1024;

    const int tid = threadIdx.x, lane = tid & 31, w = tid >> 5;
    const int g = lane >> 2, t = lane & 3;

    const int b_row  = (lane & 7) + ((lane >> 4) & 1) * 8;
    const int b_coff = ((lane >> 3) & 1) * 4;

    // prefetch K/V tile 0
    #pragma unroll
    for (int r = 0; r < 2; r++) {
        int idx = tid + r * 256;
        int row = idx >> 3, ch = idx & 7;
        cp16s(Ks + row * 36 + ch * 4, Kp + (size_t)row * 64 + ch * 8);
        cp16s(Vs + row * 36 + ch * 4, Vp + (size_t)row * 1024 + ch * 8);
    }
    cp_commit();

    // Q tile
    #pragma unroll
    for (int r = 0; r < 4; r++) {
        int idx = tid + r * 256;
        int row = idx >> 3, ch = idx & 7;
        cp16s(Qs + row * 36 + ch * 4, Qp + (size_t)row * 64 + ch * 8);
    }
    cp_commit();
    cp_wait<0>();
    __syncthreads();

    uint32_t qf[4][4];
    {
        const int ib = w * 16;
        #pragma unroll
        for (int s = 0; s < 4; s++) {
            qf[s][0] = Qs[(ib + g) * 36 + t + 8 * s];
            qf[s][1] = Qs[(ib + g + 8) * 36 + t + 8 * s];
            qf[s][2] = Qs[(ib + g) * 36 + t + 4 + 8 * s];
            qf[s][3] = Qs[(ib + g + 8) * 36 + t + 4 + 8 * s];
        }
    }

    // O and l as fp16 C-fragments
    uint32_t of[8][2];
    #pragma unroll
    for (int i = 0; i < 8; i++) { of[i][0] = 0u; of[i][1] = 0u; }
    uint32_t lacc[2] = {0u, 0u};

    for (int kt = 0; kt < 16; kt++) {
        __syncthreads();
        if (kt + 1 < 16) {
            int ps = (kt + 1) & 1, j0 = (kt + 1) * 64;
            uint32_t* ks = Ks + ps * AK_STG;
            uint32_t* vs = Vs + ps * AV_STG;
            #pragma unroll
            for (int r = 0; r < 2; r++) {
                int idx = tid + r * 256;
                int row = idx >> 3, ch = idx & 7;
                cp16s(ks + row * 36 + ch * 4, Kp + (size_t)(j0 + row) * 64 + ch * 8);
                cp16s(vs + row * 36 + ch * 4, Vp + (size_t)row * 1024 + j0 + ch * 8);
            }
        }
        cp_commit();
        cp_wait<1>();
        __syncthreads();

        uint32_t ksb = smem_u32(Ks + (kt & 1) * AK_STG);
        uint32_t vsb = smem_u32(Vs + (kt & 1) * AV_STG);

        // S = Q K^T in fp16 C-frags
        uint32_t sc[8][2];
        #pragma unroll
        for (int i = 0; i < 8; i++) { sc[i][0] = 0u; sc[i][1] = 0u; }
        #pragma unroll
        for (int s = 0; s < 4; s++) {
            uint32_t kb[16];
            #pragma unroll
            for (int p = 0; p < 4; p++)
                ldmx4(kb[4 * p], kb[4 * p + 1], kb[4 * p + 2], kb[4 * p + 3],
                      ksb + ((p * 16 + b_row) * 36 + 8 * s + b_coff) * 4);
            #pragma unroll
            for (int nt = 0; nt < 8; nt++) {
                uint32_t b0 = kb[4 * (nt >> 1) + 2 * (nt & 1)];
                uint32_t b1 = kb[4 * (nt >> 1) + 2 * (nt & 1) + 1];
                mma_f16acc(sc[nt], qf[s][0], qf[s][1], qf[s][2], qf[s][3], b0, b1);
            }
        }

        // O += P V^T ; l += P @ ones ; p = ex2(s) * 2^-8 (exact pow2 scale)
        #pragma unroll
        for (int s = 0; s < 4; s++) {
            uint32_t a0 = mulh2(ex2h2(sc[2 * s][0]),     SC2M8);
            uint32_t a1 = mulh2(ex2h2(sc[2 * s][1]),     SC2M8);
            uint32_t a2 = mulh2(ex2h2(sc[2 * s + 1][0]), SC2M8);
            uint32_t a3 = mulh2(ex2h2(sc[2 * s + 1][1]), SC2M8);
            uint32_t vb[16];
            #pragma unroll
            for (int p = 0; p < 4; p++)
                ldmx4(vb[4 * p], vb[4 * p + 1], vb[4 * p + 2], vb[4 * p + 3],
                      vsb + ((p * 16 + b_row) * 36 + 8 * s + b_coff) * 4);
            #pragma unroll
            for (int ct = 0; ct < 8; ct++) {
                uint32_t b0 = vb[4 * (ct >> 1) + 2 * (ct & 1)];
                uint32_t b1 = vb[4 * (ct >> 1) + 2 * (ct & 1) + 1];
                mma_f16acc(of[ct], a0, a1, a2, a3, b0, b1);
            }
            mma_f16acc(lacc, a0, a1, a2, a3, ONE2, ONE2);
        }
    }

    // l: all columns of the ones-product are identical -> take low halves
    float inv0 = 1.f / __low2float(*(__half2*)&lacc[0]);
    float inv1 = 1.f / __low2float(*(__half2*)&lacc[1]);

    int n0i = qt * 128 + w * 16 + g;
    __half* ob = g_attT + (size_t)b * Nq * Cq + h * 64;
    #pragma unroll
    for (int ct = 0; ct < 8; ct++) {
        int cch = ct * 8 + 2 * t;
        __half2 p0 = *(__half2*)&of[ct][0];
        __half2 p1 = *(__half2*)&of[ct][1];
        *(uint32_t*)&ob[(size_t)n0i * Cq + cch] =
            packh2(__low2float(p0) * inv0, __high2float(p0) * inv0);
        *(uint32_t*)&ob[(size_t)(n0i + 8) * Cq + cch] =
            packh2(__low2float(p1) * inv1, __high2float(p1) * inv1);
    }
}

// ---------------------------------------------------------------------------
extern "C" void kernel_launch(void* const* d_in, const int* in_sizes, int n_in,
                              void* d_out, int out_size) {
    const float* x      = (const float*)d_in[0];
    const float* gamma  = (const float*)d_in[1];
    const float* beta   = (const float*)d_in[2];
    const float* w_qkv  = (const float*)d_in[3];
    const float* b_qkv  = (const float*)d_in[4];
    const float* w_proj = (const float*)d_in[5];
    const float* b_proj = (const float*)d_in[6];
    float* out = (float*)d_out;

    void *p_hnT, *p_attT, *p_wq, *p_wp, *p_q, *p_k, *p_v;
    cudaGetSymbolAddress(&p_hnT,  g_hnT);
    cudaGetSymbolAddress(&p_attT, g_attT);
    cudaGetSymbolAddress(&p_wq,   g_wq);
    cudaGetSymbolAddress(&p_wp,   g_wp);
    cudaGetSymbolAddress(&p_q,    g_q);
    cudaGetSymbolAddress(&p_k,    g_k);
    cudaGetSymbolAddress(&p_v,    g_v);
    __half* hnT  = (__half*)p_hnT;
    __half* attT = (__half*)p_attT;
    __half* wq   = (__half*)p_wq;
    __half* wp   = (__half*)p_wp;
    __half* gq   = (__half*)p_q;
    __half* gk   = (__half*)p_k;
    __half* gv   = (__half*)p_v;

    static bool attr_set = false;
    if (!attr_set) {
        cudaFuncSetAttribute(attn_f16, cudaFuncAttributeMaxDynamicSharedMemorySize,
                             ATTN_SMEM_BYTES);
        cudaFuncSetAttribute(gemm_f16<0>,
                             cudaFuncAttributeMaxDynamicSharedMemorySize, G_SMEM_BYTES);
        cudaFuncSetAttribute(gemm_f16<1>,
                             cudaFuncAttributeMaxDynamicSharedMemorySize, G_SMEM_BYTES);
        attr_set = true;
    }

    // 0. Weights -> fp16 (single launch)
    {
        int n1 = 3 * Cq * Cq / 4, n2 = Cq * Cq / 4;
        cvt_f16_kernel<<<(n1 + n2 + 255) / 256, 256>>>(w_qkv, wq, n1, w_proj, wp, n2);
    }

    // 1. GroupNorm -> hnT (fp16, transposed)
    gn_kernel<<<Bq * GROUPS, 256>>>(x, gamma, beta, hnT);

    // 2. QKV GEMM -> Q/K [b][h][n][c] (Q scaled), V [b][h][c][n]
    gemm_f16<0><<<dim3(Nq / 64, (3 * Cq) / 128, Bq), 256, G_SMEM_BYTES>>>(
        wq, hnT, b_qkv, nullptr, nullptr, gq, gk, gv, 3 * Cq, Cq, Nq);

    // 3. Flash attention -> attT
    attn_f16<<<dim3(Nq / 128, HEADS, Bq), 256, ATTN_SMEM_BYTES>>>();

    // 4. Proj GEMM + residual -> f32 out
    gemm_f16<1><<<dim3(Nq / 64, Cq / 128, Bq), 256, G_SMEM_BYTES>>>(
        wp, attT, b_proj, x, out, nullptr, nullptr, nullptr, Cq, Cq, Nq);
}

// round 11
// speedup vs baseline: 1.0686x; 1.0686x over previous
#include <cuda_runtime.h>
#include <cuda_fp16.h>
#include <stdint.h>
#include <math.h>

// Problem constants
#define Bq    8
#define Cq    512
#define Nq    1024
#define HEADS 8
#define HD    64
#define GROUPS 32
#define CPG   16
#define EPS   1e-5f
#define LOG2E 1.4426950408889634f
#define QSC   0.18033688011112042f   // 0.125 * LOG2E
#define ONE2  0x3C003C00u            // fp16 {1.0, 1.0}
#define SC2M8 0x1C001C00u            // fp16 {2^-8, 2^-8}: exact fixed-max shift

// Scratch (device globals — no cudaMalloc allowed)
__device__ __half g_hnT [Bq * Nq * Cq];          // [b][n][c]
__device__ __half g_q   [Bq * HEADS * Nq * HD];  // [b][h][n][c], scale folded
__device__ __half g_k   [Bq * HEADS * Nq * HD];  // [b][h][n][c]
__device__ __half g_v   [Bq * HEADS * HD * Nq];  // [b][h][c][n]
__device__ __half g_attT[Bq * Nq * Cq];          // [b][n][c]
__device__ __half g_wq  [3 * Cq * Cq];
__device__ __half g_wp  [Cq * Cq];

// ---------------------------------------------------------------------------
// helpers
// ---------------------------------------------------------------------------
__device__ __forceinline__ uint32_t ex2h2(uint32_t x) {
    uint32_t r; asm("ex2.approx.f16x2 %0, %1;" : "=r"(r) : "r"(x)); return r;
}
__device__ __forceinline__ uint32_t mulh2(uint32_t a, uint32_t b) {
    uint32_t r; asm("mul.f16x2 %0, %1, %2;" : "=r"(r) : "r"(a), "r"(b)); return r;
}
// pack: lo half <- a, hi half <- b
__device__ __forceinline__ uint32_t packh2(float a, float b) {
    uint32_t r;
    asm("cvt.rn.satfinite.f16x2.f32 %0, %1, %2;" : "=r"(r) : "f"(b), "f"(a));
    return r;
}
__device__ __forceinline__ void mma_f16(float c[4],
                                        uint32_t a0, uint32_t a1, uint32_t a2, uint32_t a3,
                                        uint32_t b0, uint32_t b1) {
    asm volatile(
        "mma.sync.aligned.m16n8k16.row.col.f32.f16.f16.f32 "
        "{%0,%1,%2,%3}, {%4,%5,%6,%7}, {%8,%9}, {%0,%1,%2,%3};"
        : "+f"(c[0]), "+f"(c[1]), "+f"(c[2]), "+f"(c[3])
        : "r"(a0), "r"(a1), "r"(a2), "r"(a3), "r"(b0), "r"(b1));
}
// fp16 accumulator variant: C/D are 2x f16x2 regs
__device__ __forceinline__ void mma_f16acc(uint32_t c[2],
                                           uint32_t a0, uint32_t a1, uint32_t a2, uint32_t a3,
                                           uint32_t b0, uint32_t b1) {
    asm volatile(
        "mma.sync.aligned.m16n8k16.row.col.f16.f16.f16.f16 "
        "{%0,%1}, {%2,%3,%4,%5}, {%6,%7}, {%0,%1};"
        : "+r"(c[0]), "+r"(c[1])
        : "r"(a0), "r"(a1), "r"(a2), "r"(a3), "r"(b0), "r"(b1));
}
__device__ __forceinline__ void ldmx4(uint32_t& r0, uint32_t& r1, uint32_t& r2,
                                      uint32_t& r3, uint32_t addr) {
    asm volatile("ldmatrix.sync.aligned.m8n8.x4.shared.b16 {%0,%1,%2,%3}, [%4];"
                 : "=r"(r0), "=r"(r1), "=r"(r2), "=r"(r3) : "r"(addr));
}
__device__ __forceinline__ uint32_t smem_u32(const void* p) {
    return (uint32_t)__cvta_generic_to_shared(p);
}
__device__ __forceinline__ void cp16s(uint32_t* dst_smem, const void* src) {
    uint32_t d = smem_u32(dst_smem);
    asm volatile("cp.async.cg.shared.global [%0], [%1], 16;" :: "r"(d), "l"(src));
}
__device__ __forceinline__ void cp_commit() {
    asm volatile("cp.async.commit_group;");
}
template <int N>
__device__ __forceinline__ void cp_wait() {
    asm volatile("cp.async.wait_group %0;" :: "n"(N));
}

// ---------------------------------------------------------------------------
// Kernel 0: both weights f32 -> fp16, one launch
// ---------------------------------------------------------------------------
__global__ void cvt_f16_kernel(const float* __restrict__ s1, __half* __restrict__ d1, int n1,
                               const float* __restrict__ s2, __half* __restrict__ d2, int n2) {
    int i = blockIdx.x * 256 + threadIdx.x;
    const float* s; __half* d;
    if (i < n1) { s = s1; d = d1; }
    else if (i < n1 + n2) { s = s2; d = d2; i -= n1; }
    else return;
    float4 v = ((const float4*)s)[i];
    uint2 u;
    u.x = packh2(v.x, v.y);
    u.y = packh2(v.z, v.w);
    ((uint2*)d)[i] = u;
}

// ---------------------------------------------------------------------------
// Kernel 1: GroupNorm -> transposed fp16 output hnT[b][n][c]
// ---------------------------------------------------------------------------
__global__ void gn_kernel(const float* __restrict__ x,
                          const float* __restrict__ gamma,
                          const float* __restrict__ beta,
                          __half* __restrict__ hnT) {
    __shared__ float rs[256], rs2[256];
    __shared__ float ts[256][17];

    int bg = blockIdx.x;
    int b = bg >> 5, g = bg & 31;
    const size_t base = ((size_t)b * Cq + (size_t)g * CPG) * Nq;
    const float* xp = x + base;
    const int tid = threadIdx.x;

    float s = 0.f, s2 = 0.f;
    for (int i = tid; i < CPG * Nq; i += 256) {
        float v = xp[i];
        s += v; s2 += v * v;
    }
    rs[tid] = s; rs2[tid] = s2;
    __syncthreads();
    for (int st = 128; st > 0; st >>= 1) {
        if (tid < st) { rs[tid] += rs[tid + st]; rs2[tid] += rs2[tid + st]; }
        __syncthreads();
    }
    float mu   = rs[0]  * (1.f / 16384.f);
    float var  = rs2[0] * (1.f / 16384.f) - mu * mu;
    float rinv = rsqrtf(var + EPS);

    const int cl = tid >> 4;
    const int sg = tid & 15;
    const int cg = g * CPG + cl;
    const float ga = gamma[cg] * rinv;
    const float be = beta[cg] - mu * ga;

    __half* hb = hnT + (size_t)b * Nq * Cq;

    for (int chunk = 0; chunk < 4; chunk++) {
        int n0 = chunk * 256;
        const float* src = xp + (size_t)cl * Nq + n0 + sg * 16;
        #pragma unroll
        for (int q = 0; q < 4; q++) {
            float4 v = *(const float4*)(src + q * 4);
            int nl = sg * 16 + q * 4;
            ts[nl + 0][cl] = v.x * ga + be;
            ts[nl + 1][cl] = v.y * ga + be;
            ts[nl + 2][cl] = v.z * ga + be;
            ts[nl + 3][cl] = v.w * ga + be;
        }
        __syncthreads();
        #pragma unroll
        for (int rep = 0; rep < 4; rep++) {
            int nl = (tid >> 2) + rep * 64;
            int j4 = (tid & 3) * 4;
            uint2 u;
            u.x = packh2(ts[nl][j4],     ts[nl][j4 + 1]);
            u.y = packh2(ts[nl][j4 + 2], ts[nl][j4 + 3]);
            *(uint2*)&hb[(size_t)(n0 + nl) * Cq + g * CPG + j4] = u;
        }
        __syncthreads();
    }
}

// ---------------------------------------------------------------------------
// Kernel 2/4: fp16 GEMM (Round-9 shape: BM=128 BN=128 BK=32, 8 warps 4Mx2N).
// ---------------------------------------------------------------------------
#define GA_STG  2560      // u32 per stage (128*20)
#define GB_OFF  7680
#define G_SMEM_BYTES (2 * 3 * GA_STG * 4)

template <int MODE>
__global__ __launch_bounds__(256)
void gemm_f16(const __half* __restrict__ W, const __half* __restrict__ BT,
              const float* __restrict__ bias, const float* __restrict__ resid,
              float* __restrict__ Y,
              __half* __restrict__ gq, __half* __restrict__ gk,
              __half* __restrict__ gv,
              int M, int K, int N) {
    extern __shared__ uint32_t smg[];
    uint32_t* As = smg;
    uint32_t* Bs = smg + GB_OFF;

    const int b  = blockIdx.z;
    const int m0 = blockIdx.y * 128, n0 = blockIdx.x * 128;
    const __half* BTb = BT + (size_t)b * Nq * Cq;

    const int tid  = threadIdx.x;
    const int lane = tid & 31, warp = tid >> 5;
    const int g = lane >> 2, t = lane & 3;
    const int wm = (warp >> 1) * 32;
    const int wn = (warp & 1) * 64;

    const int a_row  = lane & 15;
    const int a_coff = ((lane >> 4) & 1) * 4;
    const int b_row  = (lane & 7) + ((lane >> 4) & 1) * 8;
    const int b_coff = ((lane >> 3) & 1) * 4;

    float acc[2][8][4];
    #pragma unroll
    for (int i = 0; i < 2; i++)
        #pragma unroll
        for (int j = 0; j < 8; j++)
            #pragma unroll
            for (int k = 0; k < 4; k++) acc[i][j][k] = 0.f;

    const int NIT = K / 32;

    auto load_stage = [&](int stage, int k0) {
        uint32_t* as = As + stage * GA_STG;
        uint32_t* bs = Bs + stage * GA_STG;
        #pragma unroll
        for (int r = 0; r < 2; r++) {
            int idx = tid + r * 256;
            int row = idx >> 2, ch = idx & 3;
            cp16s(as + row * 20 + ch * 4, W   + (size_t)(m0 + row) * K + k0 + ch * 8);
            cp16s(bs + row * 20 + ch * 4, BTb + (size_t)(n0 + row) * K + k0 + ch * 8);
        }
    };

    load_stage(0, 0);  cp_commit();
    load_stage(1, 32); cp_commit();

    for (int it = 0; it < NIT; it++) {
        cp_wait<1>();
        __syncthreads();
        if (it + 2 < NIT) load_stage((it + 2) % 3, (it + 2) * 32);
        cp_commit();

        uint32_t asb = smem_u32(As + (it % 3) * GA_STG);
        uint32_t bsb = smem_u32(Bs + (it % 3) * GA_STG);
        #pragma unroll
        for (int s = 0; s < 2; s++) {
            uint32_t af[2][4];
            #pragma unroll
            for (int mt = 0; mt < 2; mt++)
                ldmx4(af[mt][0], af[mt][1], af[mt][2], af[mt][3],
                      asb + ((wm + mt * 16 + a_row) * 20 + 8 * s + a_coff) * 4);
            uint32_t bb[16];
            #pragma unroll
            for (int p = 0; p < 4; p++)
                ldmx4(bb[4 * p], bb[4 * p + 1], bb[4 * p + 2], bb[4 * p + 3],
                      bsb + ((wn + p * 16 + b_row) * 20 + 8 * s + b_coff) * 4);
            #pragma unroll
            for (int nt = 0; nt < 8; nt++) {
                uint32_t b0 = bb[4 * (nt >> 1) + 2 * (nt & 1)];
                uint32_t b1 = bb[4 * (nt >> 1) + 2 * (nt & 1) + 1];
                mma_f16(acc[0][nt], af[0][0], af[0][1], af[0][2], af[0][3], b0, b1);
                mma_f16(acc[1][nt], af[1][0], af[1][1], af[1][2], af[1][3], b0, b1);
            }
        }
    }

    if (MODE == 0) {
        const int sel = m0 >> 9;
        #pragma unroll
        for (int mt = 0; mt < 2; mt++) {
            int m  = m0 + wm + mt * 16 + g;
            float bv0 = bias[m], bv1 = bias[m + 8];
            int hh = (m >> 6) & 7;
            int c0 = m & 63;
            #pragma unroll
            for (int nt = 0; nt < 8; nt++) {
                int n = n0 + wn + nt * 8 + 2 * t;
                float v00 = acc[mt][nt][0] + bv0, v01 = acc[mt][nt][1] + bv0;
                float v10 = acc[mt][nt][2] + bv1, v11 = acc[mt][nt][3] + bv1;
                if (sel == 0) {
                    size_t qb = ((size_t)(b * 8 + hh) * 1024);
                    gq[(qb + n) * 64 + c0]         = __float2half_rn(v00 * QSC);
                    gq[(qb + n + 1) * 64 + c0]     = __float2half_rn(v01 * QSC);
                    gq[(qb + n) * 64 + c0 + 8]     = __float2half_rn(v10 * QSC);
                    gq[(qb + n + 1) * 64 + c0 + 8] = __float2half_rn(v11 * QSC);
                } else if (sel == 1) {
                    size_t kb = ((size_t)(b * 8 + hh) * 1024);
                    gk[(kb + n) * 64 + c0]         = __float2half_rn(v00);
                    gk[(kb + n + 1) * 64 + c0]     = __float2half_rn(v01);
                    gk[(kb + n) * 64 + c0 + 8]     = __float2half_rn(v10);
                    gk[(kb + n + 1) * 64 + c0 + 8] = __float2half_rn(v11);
                } else {
                    size_t vb = ((size_t)(b * 8 + hh) * 64);
                    *(uint32_t*)&gv[(vb + c0) * 1024 + n]     = packh2(v00, v01);
                    *(uint32_t*)&gv[(vb + c0 + 8) * 1024 + n] = packh2(v10, v11);
                }
            }
        }
    } else {
        float*       Yb = Y + (size_t)b * Cq * Nq;
        const float* Rb = resid + (size_t)b * Cq * Nq;
        #pragma unroll
        for (int mt = 0; mt < 2; mt++) {
            int r0 = m0 + wm + mt * 16 + g;
            int r1 = r0 + 8;
            float bv0 = bias[r0], bv1 = bias[r1];
            #pragma unroll
            for (int nt = 0; nt < 8; nt++) {
                int cc = n0 + wn + nt * 8 + 2 * t;
                float2 q0 = *(const float2*)&Rb[(size_t)r0 * N + cc];
                float2 q1 = *(const float2*)&Rb[(size_t)r1 * N + cc];
                float2 v0 = make_float2(acc[mt][nt][0] + bv0 + q0.x,
                                        acc[mt][nt][1] + bv0 + q0.y);
                float2 v1 = make_float2(acc[mt][nt][2] + bv1 + q1.x,
                                        acc[mt][nt][3] + bv1 + q1.y);
                *(float2*)&Yb[(size_t)r0 * N + cc] = v0;
                *(float2*)&Yb[(size_t)r1 * N + cc] = v1;
            }
        }
    }
}

// ---------------------------------------------------------------------------
// Kernel 3: fp16 flash attention, 128 threads / 4 warps, 32-row warp tiles.
// K/V fragment loads amortized over 2 m-tiles -> half the smem read traffic.
// Fixed-max softmax, fp16 S and O/l accumulators.
// ---------------------------------------------------------------------------
#define AK_OFF  4608
#define AK_STG  2304          // 64*36
#define AV_OFF  9216
#define AV_STG  2304
#define ATTN_SMEM_BYTES (13824 * 4)

__global__ __launch_bounds__(128, 4)
void attn_f16() {
    extern __shared__ uint32_t sma[];
    uint32_t* Qs = sma;
    uint32_t* Ks = sma + AK_OFF;
    uint32_t* Vs = sma + AV_OFF;

    const int qt = blockIdx.x, h = blockIdx.y, b = blockIdx.z;
    const __half* Qp = g_q + ((size_t)(b * 8 + h) * 1024 + qt * 128) * 64;
    const __half* Kp = g_k + ((size_t)(b * 8 + h) * 1024) * 64;
    const __half* Vp = g_v + ((size_t)(b * 8 + h) * 64) * 1024;

    const int tid = threadIdx.x, lane = tid & 31, w = tid >> 5;
    const int g = lane >> 2, t = lane & 3;

    const int b_row  = (lane & 7) + ((lane >> 4) & 1) * 8;
    const int b_coff = ((lane >> 3) & 1) * 4;

    // prefetch K/V tile 0 (128 threads, 4 reps each)
    #pragma unroll
    for (int r = 0; r < 4; r++) {
        int idx = tid + r * 128;
        int row = idx >> 3, ch = idx & 7;
        cp16s(Ks + row * 36 + ch * 4, Kp + (size_t)row * 64 + ch * 8);
        cp16s(Vs + row * 36 + ch * 4, Vp + (size_t)row * 1024 + ch * 8);
    }
    cp_commit();

    // Q tile (128 rows, 8 reps)
    #pragma unroll
    for (int r = 0; r < 8; r++) {
        int idx = tid + r * 128;
        int row = idx >> 3, ch = idx & 7;
        cp16s(Qs + row * 36 + ch * 4, Qp + (size_t)row * 64 + ch * 8);
    }
    cp_commit();
    cp_wait<0>();
    __syncthreads();

    // Q fragments: 2 m16 tiles x 4 k-steps
    uint32_t qf[2][4][4];
    #pragma unroll
    for (int mt = 0; mt < 2; mt++) {
        const int ib = w * 32 + mt * 16;
        #pragma unroll
        for (int s = 0; s < 4; s++) {
            qf[mt][s][0] = Qs[(ib + g) * 36 + t + 8 * s];
            qf[mt][s][1] = Qs[(ib + g + 8) * 36 + t + 8 * s];
            qf[mt][s][2] = Qs[(ib + g) * 36 + t + 4 + 8 * s];
            qf[mt][s][3] = Qs[(ib + g + 8) * 36 + t + 4 + 8 * s];
        }
    }

    // O and l as fp16 C-fragments, per m-tile
    uint32_t of[2][8][2];
    #pragma unroll
    for (int mt = 0; mt < 2; mt++)
        #pragma unroll
        for (int i = 0; i < 8; i++) { of[mt][i][0] = 0u; of[mt][i][1] = 0u; }
    uint32_t lacc[2][2] = {{0u, 0u}, {0u, 0u}};

    for (int kt = 0; kt < 16; kt++) {
        __syncthreads();
        if (kt + 1 < 16) {
            int ps = (kt + 1) & 1, j0 = (kt + 1) * 64;
            uint32_t* ks = Ks + ps * AK_STG;
            uint32_t* vs = Vs + ps * AV_STG;
            #pragma unroll
            for (int r = 0; r < 4; r++) {
                int idx = tid + r * 128;
                int row = idx >> 3, ch = idx & 7;
                cp16s(ks + row * 36 + ch * 4, Kp + (size_t)(j0 + row) * 64 + ch * 8);
                cp16s(vs + row * 36 + ch * 4, Vp + (size_t)row * 1024 + j0 + ch * 8);
            }
        }
        cp_commit();
        cp_wait<1>();
        __syncthreads();

        uint32_t ksb = smem_u32(Ks + (kt & 1) * AK_STG);
        uint32_t vsb = smem_u32(Vs + (kt & 1) * AV_STG);

        // S = Q K^T in fp16 C-frags, both m-tiles share kb fragments
        uint32_t sc[2][8][2];
        #pragma unroll
        for (int mt = 0; mt < 2; mt++)
            #pragma unroll
            for (int i = 0; i < 8; i++) { sc[mt][i][0] = 0u; sc[mt][i][1] = 0u; }
        #pragma unroll
        for (int s = 0; s < 4; s++) {
            uint32_t kb[16];
            #pragma unroll
            for (int p = 0; p < 4; p++)
                ldmx4(kb[4 * p], kb[4 * p + 1], kb[4 * p + 2], kb[4 * p + 3],
                      ksb + ((p * 16 + b_row) * 36 + 8 * s + b_coff) * 4);
            #pragma unroll
            for (int nt = 0; nt < 8; nt++) {
                uint32_t b0 = kb[4 * (nt >> 1) + 2 * (nt & 1)];
                uint32_t b1 = kb[4 * (nt >> 1) + 2 * (nt & 1) + 1];
                mma_f16acc(sc[0][nt], qf[0][s][0], qf[0][s][1], qf[0][s][2], qf[0][s][3], b0, b1);
                mma_f16acc(sc[1][nt], qf[1][s][0], qf[1][s][1], qf[1][s][2], qf[1][s][3], b0, b1);
            }
        }

        // O += P V^T ; l += P @ ones ; p = ex2(s) * 2^-8, vb shared across mt
        #pragma unroll
        for (int s = 0; s < 4; s++) {
            uint32_t vb[16];
            #pragma unroll
            for (int p = 0; p < 4; p++)
                ldmx4(vb[4 * p], vb[4 * p + 1], vb[4 * p + 2], vb[4 * p + 3],
                      vsb + ((p * 16 + b_row) * 36 + 8 * s + b_coff) * 4);
            #pragma unroll
            for (int mt = 0; mt < 2; mt++) {
                uint32_t a0 = mulh2(ex2h2(sc[mt][2 * s][0]),     SC2M8);
                uint32_t a1 = mulh2(ex2h2(sc[mt][2 * s][1]),     SC2M8);
                uint32_t a2 = mulh2(ex2h2(sc[mt][2 * s + 1][0]), SC2M8);
                uint32_t a3 = mulh2(ex2h2(sc[mt][2 * s + 1][1]), SC2M8);
                #pragma unroll
                for (int ct = 0; ct < 8; ct++) {
                    uint32_t b0 = vb[4 * (ct >> 1) + 2 * (ct & 1)];
                    uint32_t b1 = vb[4 * (ct >> 1) + 2 * (ct & 1) + 1];
                    mma_f16acc(of[mt][ct], a0, a1, a2, a3, b0, b1);
                }
                mma_f16acc(lacc[mt], a0, a1, a2, a3, ONE2, ONE2);
            }
        }
    }

    // normalize + store attT[b][n][c]
    __half* ob = g_attT + (size_t)b * Nq * Cq + h * 64;
    #pragma unroll
    for (int mt = 0; mt < 2; mt++) {
        float inv0 = 1.f / __low2float(*(__half2*)&lacc[mt][0]);
        float inv1 = 1.f / __low2float(*(__half2*)&lacc[mt][1]);
        int n0i = qt * 128 + w * 32 + mt * 16 + g;
        #pragma unroll
        for (int ct = 0; ct < 8; ct++) {
            int cch = ct * 8 + 2 * t;
            __half2 p0 = *(__half2*)&of[mt][ct][0];
            __half2 p1 = *(__half2*)&of[mt][ct][1];
            *(uint32_t*)&ob[(size_t)n0i * Cq + cch] =
                packh2(__low2float(p0) * inv0, __high2float(p0) * inv0);
            *(uint32_t*)&ob[(size_t)(n0i + 8) * Cq + cch] =
                packh2(__low2float(p1) * inv1, __high2float(p1) * inv1);
        }
    }
}

// ---------------------------------------------------------------------------
extern "C" void kernel_launch(void* const* d_in, const int* in_sizes, int n_in,
                              void* d_out, int out_size) {
    const float* x      = (const float*)d_in[0];
    const float* gamma  = (const float*)d_in[1];
    const float* beta   = (const float*)d_in[2];
    const float* w_qkv  = (const float*)d_in[3];
    const float* b_qkv  = (const float*)d_in[4];
    const float* w_proj = (const float*)d_in[5];
    const float* b_proj = (const float*)d_in[6];
    float* out = (float*)d_out;

    void *p_hnT, *p_attT, *p_wq, *p_wp, *p_q, *p_k, *p_v;
    cudaGetSymbolAddress(&p_hnT,  g_hnT);
    cudaGetSymbolAddress(&p_attT, g_attT);
    cudaGetSymbolAddress(&p_wq,   g_wq);
    cudaGetSymbolAddress(&p_wp,   g_wp);
    cudaGetSymbolAddress(&p_q,    g_q);
    cudaGetSymbolAddress(&p_k,    g_k);
    cudaGetSymbolAddress(&p_v,    g_v);
    __half* hnT  = (__half*)p_hnT;
    __half* attT = (__half*)p_attT;
    __half* wq   = (__half*)p_wq;
    __half* wp   = (__half*)p_wp;
    __half* gq   = (__half*)p_q;
    __half* gk   = (__half*)p_k;
    __half* gv   = (__half*)p_v;

    static bool attr_set = false;
    if (!attr_set) {
        cudaFuncSetAttribute(attn_f16, cudaFuncAttributeMaxDynamicSharedMemorySize,
                             ATTN_SMEM_BYTES);
        cudaFuncSetAttribute(gemm_f16<0>,
                             cudaFuncAttributeMaxDynamicSharedMemorySize, G_SMEM_BYTES);
        cudaFuncSetAttribute(gemm_f16<1>,
                             cudaFuncAttributeMaxDynamicSharedMemorySize, G_SMEM_BYTES);
        attr_set = true;
    }

    // 0. Weights -> fp16 (single launch)
    {
        int n1 = 3 * Cq * Cq / 4, n2 = Cq * Cq / 4;
        cvt_f16_kernel<<<(n1 + n2 + 255) / 256, 256>>>(w_qkv, wq, n1, w_proj, wp, n2);
    }

    // 1. GroupNorm -> hnT (fp16, transposed)
    gn_kernel<<<Bq * GROUPS, 256>>>(x, gamma, beta, hnT);

    // 2. QKV GEMM -> Q/K [b][h][n][c] (Q scaled), V [b][h][c][n]
    gemm_f16<0><<<dim3(Nq / 128, (3 * Cq) / 128, Bq), 256, G_SMEM_BYTES>>>(
        wq, hnT, b_qkv, nullptr, nullptr, gq, gk, gv, 3 * Cq, Cq, Nq);

    // 3. Flash attention -> attT (128 threads, 32-row warp tiles)
    attn_f16<<<dim3(Nq / 128, HEADS, Bq), 128, ATTN_SMEM_BYTES>>>();

    // 4. Proj GEMM + residual -> f32 out
    gemm_f16<1><<<dim3(Nq / 128, Cq / 128, Bq), 256, G_SMEM_BYTES>>>(
        wp, attT, b_proj, x, out, nullptr, nullptr, nullptr, Cq, Cq, Nq);
}

// round 12
// speedup vs baseline: 1.0715x; 1.0027x over previous
#include <cuda_runtime.h>
#include <cuda_fp16.h>
#include <stdint.h>
#include <math.h>

// Problem constants
#define Bq    8
#define Cq    512
#define Nq    1024
#define HEADS 8
#define HD    64
#define GROUPS 32
#define CPG   16
#define EPS   1e-5f
#define LOG2E 1.4426950408889634f
#define QSC   0.18033688011112042f   // 0.125 * LOG2E
#define ONE2  0x3C003C00u            // fp16 {1.0, 1.0}
#define SC2M8 0x1C001C00u            // fp16 {2^-8, 2^-8}: exact fixed-max shift

// Scratch (device globals — no cudaMalloc allowed)
__device__ __half g_hnT [Bq * Nq * Cq];          // [b][n][c]
__device__ __half g_q   [Bq * HEADS * Nq * HD];  // [b][h][n][c], scale folded
__device__ __half g_k   [Bq * HEADS * Nq * HD];  // [b][h][n][c]
__device__ __half g_v   [Bq * HEADS * HD * Nq];  // [b][h][c][n]
__device__ __half g_attT[Bq * Nq * Cq];          // [b][n][c]
__device__ __half g_wq  [3 * Cq * Cq];
__device__ __half g_wp  [Cq * Cq];

// ---------------------------------------------------------------------------
// helpers
// ---------------------------------------------------------------------------
__device__ __forceinline__ uint32_t ex2h2(uint32_t x) {
    uint32_t r; asm("ex2.approx.f16x2 %0, %1;" : "=r"(r) : "r"(x)); return r;
}
__device__ __forceinline__ uint32_t mulh2(uint32_t a, uint32_t b) {
    uint32_t r; asm("mul.f16x2 %0, %1, %2;" : "=r"(r) : "r"(a), "r"(b)); return r;
}
// pack: lo half <- a, hi half <- b
__device__ __forceinline__ uint32_t packh2(float a, float b) {
    uint32_t r;
    asm("cvt.rn.satfinite.f16x2.f32 %0, %1, %2;" : "=r"(r) : "f"(b), "f"(a));
    return r;
}
// fp16 accumulator MMA: C/D are 2x f16x2 regs
__device__ __forceinline__ void mma_f16acc(uint32_t c[2],
                                           uint32_t a0, uint32_t a1, uint32_t a2, uint32_t a3,
                                           uint32_t b0, uint32_t b1) {
    asm volatile(
        "mma.sync.aligned.m16n8k16.row.col.f16.f16.f16.f16 "
        "{%0,%1}, {%2,%3,%4,%5}, {%6,%7}, {%0,%1};"
        : "+r"(c[0]), "+r"(c[1])
        : "r"(a0), "r"(a1), "r"(a2), "r"(a3), "r"(b0), "r"(b1));
}
__device__ __forceinline__ void ldmx4(uint32_t& r0, uint32_t& r1, uint32_t& r2,
                                      uint32_t& r3, uint32_t addr) {
    asm volatile("ldmatrix.sync.aligned.m8n8.x4.shared.b16 {%0,%1,%2,%3}, [%4];"
                 : "=r"(r0), "=r"(r1), "=r"(r2), "=r"(r3) : "r"(addr));
}
__device__ __forceinline__ uint32_t smem_u32(const void* p) {
    return (uint32_t)__cvta_generic_to_shared(p);
}
__device__ __forceinline__ void cp16s(uint32_t* dst_smem, const void* src) {
    uint32_t d = smem_u32(dst_smem);
    asm volatile("cp.async.cg.shared.global [%0], [%1], 16;" :: "r"(d), "l"(src));
}
__device__ __forceinline__ void cp_commit() {
    asm volatile("cp.async.commit_group;");
}
template <int N>
__device__ __forceinline__ void cp_wait() {
    asm volatile("cp.async.wait_group %0;" :: "n"(N));
}

// ---------------------------------------------------------------------------
// Kernel 0: both weights f32 -> fp16, one launch
// ---------------------------------------------------------------------------
__global__ void cvt_f16_kernel(const float* __restrict__ s1, __half* __restrict__ d1, int n1,
                               const float* __restrict__ s2, __half* __restrict__ d2, int n2) {
    int i = blockIdx.x * 256 + threadIdx.x;
    const float* s; __half* d;
    if (i < n1) { s = s1; d = d1; }
    else if (i < n1 + n2) { s = s2; d = d2; i -= n1; }
    else return;
    float4 v = ((const float4*)s)[i];
    uint2 u;
    u.x = packh2(v.x, v.y);
    u.y = packh2(v.z, v.w);
    ((uint2*)d)[i] = u;
}

// ---------------------------------------------------------------------------
// Kernel 1: GroupNorm -> transposed fp16 output hnT[b][n][c]
// ---------------------------------------------------------------------------
__global__ void gn_kernel(const float* __restrict__ x,
                          const float* __restrict__ gamma,
                          const float* __restrict__ beta,
                          __half* __restrict__ hnT) {
    __shared__ float rs[256], rs2[256];
    __shared__ float ts[256][17];

    int bg = blockIdx.x;
    int b = bg >> 5, g = bg & 31;
    const size_t base = ((size_t)b * Cq + (size_t)g * CPG) * Nq;
    const float* xp = x + base;
    const int tid = threadIdx.x;

    float s = 0.f, s2 = 0.f;
    for (int i = tid; i < CPG * Nq; i += 256) {
        float v = xp[i];
        s += v; s2 += v * v;
    }
    rs[tid] = s; rs2[tid] = s2;
    __syncthreads();
    for (int st = 128; st > 0; st >>= 1) {
        if (tid < st) { rs[tid] += rs[tid + st]; rs2[tid] += rs2[tid + st]; }
        __syncthreads();
    }
    float mu   = rs[0]  * (1.f / 16384.f);
    float var  = rs2[0] * (1.f / 16384.f) - mu * mu;
    float rinv = rsqrtf(var + EPS);

    const int cl = tid >> 4;
    const int sg = tid & 15;
    const int cg = g * CPG + cl;
    const float ga = gamma[cg] * rinv;
    const float be = beta[cg] - mu * ga;

    __half* hb = hnT + (size_t)b * Nq * Cq;

    for (int chunk = 0; chunk < 4; chunk++) {
        int n0 = chunk * 256;
        const float* src = xp + (size_t)cl * Nq + n0 + sg * 16;
        #pragma unroll
        for (int q = 0; q < 4; q++) {
            float4 v = *(const float4*)(src + q * 4);
            int nl = sg * 16 + q * 4;
            ts[nl + 0][cl] = v.x * ga + be;
            ts[nl + 1][cl] = v.y * ga + be;
            ts[nl + 2][cl] = v.z * ga + be;
            ts[nl + 3][cl] = v.w * ga + be;
        }
        __syncthreads();
        #pragma unroll
        for (int rep = 0; rep < 4; rep++) {
            int nl = (tid >> 2) + rep * 64;
            int j4 = (tid & 3) * 4;
            uint2 u;
            u.x = packh2(ts[nl][j4],     ts[nl][j4 + 1]);
            u.y = packh2(ts[nl][j4 + 2], ts[nl][j4 + 3]);
            *(uint2*)&hb[(size_t)(n0 + nl) * Cq + g * CPG + j4] = u;
        }
        __syncthreads();
    }
}

// ---------------------------------------------------------------------------
// Kernel 2/4: fp16 GEMM, BM=128 BN=128 BK=32, 8 warps (4Mx2N, 32x64/warp),
// fp16 accumulators (32 regs) -> 3 CTAs/SM.
// ---------------------------------------------------------------------------
#define GA_STG  2560      // u32 per stage (128*20)
#define GB_OFF  7680
#define G_SMEM_BYTES (2 * 3 * GA_STG * 4)

template <int MODE>
__global__ __launch_bounds__(256, 3)
void gemm_f16(const __half* __restrict__ W, const __half* __restrict__ BT,
              const float* __restrict__ bias, const float* __restrict__ resid,
              float* __restrict__ Y,
              __half* __restrict__ gq, __half* __restrict__ gk,
              __half* __restrict__ gv,
              int M, int K, int N) {
    extern __shared__ uint32_t smg[];
    uint32_t* As = smg;
    uint32_t* Bs = smg + GB_OFF;

    const int b  = blockIdx.z;
    const int m0 = blockIdx.y * 128, n0 = blockIdx.x * 128;
    const __half* BTb = BT + (size_t)b * Nq * Cq;

    const int tid  = threadIdx.x;
    const int lane = tid & 31, warp = tid >> 5;
    const int g = lane >> 2, t = lane & 3;
    const int wm = (warp >> 1) * 32;
    const int wn = (warp & 1) * 64;

    const int a_row  = lane & 15;
    const int a_coff = ((lane >> 4) & 1) * 4;
    const int b_row  = (lane & 7) + ((lane >> 4) & 1) * 8;
    const int b_coff = ((lane >> 3) & 1) * 4;

    // fp16 accumulators: acc[mt][nt][0] = row g cols (2t,2t+1); [1] = row g+8
    uint32_t acc[2][8][2];
    #pragma unroll
    for (int i = 0; i < 2; i++)
        #pragma unroll
        for (int j = 0; j < 8; j++) { acc[i][j][0] = 0u; acc[i][j][1] = 0u; }

    const int NIT = K / 32;

    auto load_stage = [&](int stage, int k0) {
        uint32_t* as = As + stage * GA_STG;
        uint32_t* bs = Bs + stage * GA_STG;
        #pragma unroll
        for (int r = 0; r < 2; r++) {
            int idx = tid + r * 256;
            int row = idx >> 2, ch = idx & 3;
            cp16s(as + row * 20 + ch * 4, W   + (size_t)(m0 + row) * K + k0 + ch * 8);
            cp16s(bs + row * 20 + ch * 4, BTb + (size_t)(n0 + row) * K + k0 + ch * 8);
        }
    };

    load_stage(0, 0);  cp_commit();
    load_stage(1, 32); cp_commit();

    for (int it = 0; it < NIT; it++) {
        cp_wait<1>();
        __syncthreads();
        if (it + 2 < NIT) load_stage((it + 2) % 3, (it + 2) * 32);
        cp_commit();

        uint32_t asb = smem_u32(As + (it % 3) * GA_STG);
        uint32_t bsb = smem_u32(Bs + (it % 3) * GA_STG);
        #pragma unroll
        for (int s = 0; s < 2; s++) {
            uint32_t af[2][4];
            #pragma unroll
            for (int mt = 0; mt < 2; mt++)
                ldmx4(af[mt][0], af[mt][1], af[mt][2], af[mt][3],
                      asb + ((wm + mt * 16 + a_row) * 20 + 8 * s + a_coff) * 4);
            uint32_t bb[16];
            #pragma unroll
            for (int p = 0; p < 4; p++)
                ldmx4(bb[4 * p], bb[4 * p + 1], bb[4 * p + 2], bb[4 * p + 3],
                      bsb + ((wn + p * 16 + b_row) * 20 + 8 * s + b_coff) * 4);
            #pragma unroll
            for (int nt = 0; nt < 8; nt++) {
                uint32_t b0 = bb[4 * (nt >> 1) + 2 * (nt & 1)];
                uint32_t b1 = bb[4 * (nt >> 1) + 2 * (nt & 1) + 1];
                mma_f16acc(acc[0][nt], af[0][0], af[0][1], af[0][2], af[0][3], b0, b1);
                mma_f16acc(acc[1][nt], af[1][0], af[1][1], af[1][2], af[1][3], b0, b1);
            }
        }
    }

    if (MODE == 0) {
        const int sel = m0 >> 9;
        #pragma unroll
        for (int mt = 0; mt < 2; mt++) {
            int m  = m0 + wm + mt * 16 + g;
            float bv0 = bias[m], bv1 = bias[m + 8];
            int hh = (m >> 6) & 7;
            int c0 = m & 63;
            #pragma unroll
            for (int nt = 0; nt < 8; nt++) {
                int n = n0 + wn + nt * 8 + 2 * t;
                __half2 h0 = *(__half2*)&acc[mt][nt][0];
                __half2 h1 = *(__half2*)&acc[mt][nt][1];
                float v00 = __low2float(h0) + bv0, v01 = __high2float(h0) + bv0;
                float v10 = __low2float(h1) + bv1, v11 = __high2float(h1) + bv1;
                if (sel == 0) {
                    size_t qb = ((size_t)(b * 8 + hh) * 1024);
                    gq[(qb + n) * 64 + c0]         = __float2half_rn(v00 * QSC);
                    gq[(qb + n + 1) * 64 + c0]     = __float2half_rn(v01 * QSC);
                    gq[(qb + n) * 64 + c0 + 8]     = __float2half_rn(v10 * QSC);
                    gq[(qb + n + 1) * 64 + c0 + 8] = __float2half_rn(v11 * QSC);
                } else if (sel == 1) {
                    size_t kb = ((size_t)(b * 8 + hh) * 1024);
                    gk[(kb + n) * 64 + c0]         = __float2half_rn(v00);
                    gk[(kb + n + 1) * 64 + c0]     = __float2half_rn(v01);
                    gk[(kb + n) * 64 + c0 + 8]     = __float2half_rn(v10);
                    gk[(kb + n + 1) * 64 + c0 + 8] = __float2half_rn(v11);
                } else {
                    size_t vb = ((size_t)(b * 8 + hh) * 64);
                    *(uint32_t*)&gv[(vb + c0) * 1024 + n]     = packh2(v00, v01);
                    *(uint32_t*)&gv[(vb + c0 + 8) * 1024 + n] = packh2(v10, v11);
                }
            }
        }
    } else {
        float*       Yb = Y + (size_t)b * Cq * Nq;
        const float* Rb = resid + (size_t)b * Cq * Nq;
        #pragma unroll
        for (int mt = 0; mt < 2; mt++) {
            int r0 = m0 + wm + mt * 16 + g;
            int r1 = r0 + 8;
            float bv0 = bias[r0], bv1 = bias[r1];
            #pragma unroll
            for (int nt = 0; nt < 8; nt++) {
                int cc = n0 + wn + nt * 8 + 2 * t;
                __half2 h0 = *(__half2*)&acc[mt][nt][0];
                __half2 h1 = *(__half2*)&acc[mt][nt][1];
                float2 q0 = *(const float2*)&Rb[(size_t)r0 * N + cc];
                float2 q1 = *(const float2*)&Rb[(size_t)r1 * N + cc];
                float2 v0 = make_float2(__low2float(h0) + bv0 + q0.x,
                                        __high2float(h0) + bv0 + q0.y);
                float2 v1 = make_float2(__low2float(h1) + bv1 + q1.x,
                                        __high2float(h1) + bv1 + q1.y);
                *(float2*)&Yb[(size_t)r0 * N + cc] = v0;
                *(float2*)&Yb[(size_t)r1 * N + cc] = v1;
            }
        }
    }
}

// ---------------------------------------------------------------------------
// Kernel 3: fp16 flash attention, 128 threads / 4 warps, 32-row warp tiles.
// (unchanged from Round 11)
// ---------------------------------------------------------------------------
#define AK_OFF  4608
#define AK_STG  2304          // 64*36
#define AV_OFF  9216
#define AV_STG  2304
#define ATTN_SMEM_BYTES (13824 * 4)

__global__ __launch_bounds__(128, 4)
void attn_f16() {
    extern __shared__ uint32_t sma[];
    uint32_t* Qs = sma;
    uint32_t* Ks = sma + AK_OFF;
    uint32_t* Vs = sma + AV_OFF;

    const int qt = blockIdx.x, h = blockIdx.y, b = blockIdx.z;
    const __half* Qp = g_q + ((size_t)(b * 8 + h) * 1024 + qt * 128) * 64;
    const __half* Kp = g_k + ((size_t)(b * 8 + h) * 1024) * 64;
    const __half* Vp = g_v + ((size_t)(b * 8 + h) * 64) * 1024;

    const int tid = threadIdx.x, lane = tid & 31, w = tid >> 5;
    const int g = lane >> 2, t = lane & 3;

    const int b_row  = (lane & 7) + ((lane >> 4) & 1) * 8;
    const int b_coff = ((lane >> 3) & 1) * 4;

    // prefetch K/V tile 0 (128 threads, 4 reps each)
    #pragma unroll
    for (int r = 0; r < 4; r++) {
        int idx = tid + r * 128;
        int row = idx >> 3, ch = idx & 7;
        cp16s(Ks + row * 36 + ch * 4, Kp + (size_t)row * 64 + ch * 8);
        cp16s(Vs + row * 36 + ch * 4, Vp + (size_t)row * 1024 + ch * 8);
    }
    cp_commit();

    // Q tile (128 rows, 8 reps)
    #pragma unroll
    for (int r = 0; r < 8; r++) {
        int idx = tid + r * 128;
        int row = idx >> 3, ch = idx & 7;
        cp16s(Qs + row * 36 + ch * 4, Qp + (size_t)row * 64 + ch * 8);
    }
    cp_commit();
    cp_wait<0>();
    __syncthreads();

    // Q fragments: 2 m16 tiles x 4 k-steps
    uint32_t qf[2][4][4];
    #pragma unroll
    for (int mt = 0; mt < 2; mt++) {
        const int ib = w * 32 + mt * 16;
        #pragma unroll
        for (int s = 0; s < 4; s++) {
            qf[mt][s][0] = Qs[(ib + g) * 36 + t + 8 * s];
            qf[mt][s][1] = Qs[(ib + g + 8) * 36 + t + 8 * s];
            qf[mt][s][2] = Qs[(ib + g) * 36 + t + 4 + 8 * s];
            qf[mt][s][3] = Qs[(ib + g + 8) * 36 + t + 4 + 8 * s];
        }
    }

    // O and l as fp16 C-fragments, per m-tile
    uint32_t of[2][8][2];
    #pragma unroll
    for (int mt = 0; mt < 2; mt++)
        #pragma unroll
        for (int i = 0; i < 8; i++) { of[mt][i][0] = 0u; of[mt][i][1] = 0u; }
    uint32_t lacc[2][2] = {{0u, 0u}, {0u, 0u}};

    for (int kt = 0; kt < 16; kt++) {
        __syncthreads();
        if (kt + 1 < 16) {
            int ps = (kt + 1) & 1, j0 = (kt + 1) * 64;
            uint32_t* ks = Ks + ps * AK_STG;
            uint32_t* vs = Vs + ps * AV_STG;
            #pragma unroll
            for (int r = 0; r < 4; r++) {
                int idx = tid + r * 128;
                int row = idx >> 3, ch = idx & 7;
                cp16s(ks + row * 36 + ch * 4, Kp + (size_t)(j0 + row) * 64 + ch * 8);
                cp16s(vs + row * 36 + ch * 4, Vp + (size_t)row * 1024 + j0 + ch * 8);
            }
        }
        cp_commit();
        cp_wait<1>();
        __syncthreads();

        uint32_t ksb = smem_u32(Ks + (kt & 1) * AK_STG);
        uint32_t vsb = smem_u32(Vs + (kt & 1) * AV_STG);

        // S = Q K^T in fp16 C-frags, both m-tiles share kb fragments
        uint32_t sc[2][8][2];
        #pragma unroll
        for (int mt = 0; mt < 2; mt++)
            #pragma unroll
            for (int i = 0; i < 8; i++) { sc[mt][i][0] = 0u; sc[mt][i][1] = 0u; }
        #pragma unroll
        for (int s = 0; s < 4; s++) {
            uint32_t kb[16];
            #pragma unroll
            for (int p = 0; p < 4; p++)
                ldmx4(kb[4 * p], kb[4 * p + 1], kb[4 * p + 2], kb[4 * p + 3],
                      ksb + ((p * 16 + b_row) * 36 + 8 * s + b_coff) * 4);
            #pragma unroll
            for (int nt = 0; nt < 8; nt++) {
                uint32_t b0 = kb[4 * (nt >> 1) + 2 * (nt & 1)];
                uint32_t b1 = kb[4 * (nt >> 1) + 2 * (nt & 1) + 1];
                mma_f16acc(sc[0][nt], qf[0][s][0], qf[0][s][1], qf[0][s][2], qf[0][s][3], b0, b1);
                mma_f16acc(sc[1][nt], qf[1][s][0], qf[1][s][1], qf[1][s][2], qf[1][s][3], b0, b1);
            }
        }

        // O += P V^T ; l += P @ ones ; p = ex2(s) * 2^-8, vb shared across mt
        #pragma unroll
        for (int s = 0; s < 4; s++) {
            uint32_t vb[16];
            #pragma unroll
            for (int p = 0; p < 4; p++)
                ldmx4(vb[4 * p], vb[4 * p + 1], vb[4 * p + 2], vb[4 * p + 3],
                      vsb + ((p * 16 + b_row) * 36 + 8 * s + b_coff) * 4);
            #pragma unroll
            for (int mt = 0; mt < 2; mt++) {
                uint32_t a0 = mulh2(ex2h2(sc[mt][2 * s][0]),     SC2M8);
                uint32_t a1 = mulh2(ex2h2(sc[mt][2 * s][1]),     SC2M8);
                uint32_t a2 = mulh2(ex2h2(sc[mt][2 * s + 1][0]), SC2M8);
                uint32_t a3 = mulh2(ex2h2(sc[mt][2 * s + 1][1]), SC2M8);
                #pragma unroll
                for (int ct = 0; ct < 8; ct++) {
                    uint32_t b0 = vb[4 * (ct >> 1) + 2 * (ct & 1)];
                    uint32_t b1 = vb[4 * (ct >> 1) + 2 * (ct & 1) + 1];
                    mma_f16acc(of[mt][ct], a0, a1, a2, a3, b0, b1);
                }
                mma_f16acc(lacc[mt], a0, a1, a2, a3, ONE2, ONE2);
            }
        }
    }

    // normalize + store attT[b][n][c]
    __half* ob = g_attT + (size_t)b * Nq * Cq + h * 64;
    #pragma unroll
    for (int mt = 0; mt < 2; mt++) {
        float inv0 = 1.f / __low2float(*(__half2*)&lacc[mt][0]);
        float inv1 = 1.f / __low2float(*(__half2*)&lacc[mt][1]);
        int n0i = qt * 128 + w * 32 + mt * 16 + g;
        #pragma unroll
        for (int ct = 0; ct < 8; ct++) {
            int cch = ct * 8 + 2 * t;
            __half2 p0 = *(__half2*)&of[mt][ct][0];
            __half2 p1 = *(__half2*)&of[mt][ct][1];
            *(uint32_t*)&ob[(size_t)n0i * Cq + cch] =
                packh2(__low2float(p0) * inv0, __high2float(p0) * inv0);
            *(uint32_t*)&ob[(size_t)(n0i + 8) * Cq + cch] =
                packh2(__low2float(p1) * inv1, __high2float(p1) * inv1);
        }
    }
}

// ---------------------------------------------------------------------------
extern "C" void kernel_launch(void* const* d_in, const int* in_sizes, int n_in,
                              void* d_out, int out_size) {
    const float* x      = (const float*)d_in[0];
    const float* gamma  = (const float*)d_in[1];
    const float* beta   = (const float*)d_in[2];
    const float* w_qkv  = (const float*)d_in[3];
    const float* b_qkv  = (const float*)d_in[4];
    const float* w_proj = (const float*)d_in[5];
    const float* b_proj = (const float*)d_in[6];
    float* out = (float*)d_out;

    void *p_hnT, *p_attT, *p_wq, *p_wp, *p_q, *p_k, *p_v;
    cudaGetSymbolAddress(&p_hnT,  g_hnT);
    cudaGetSymbolAddress(&p_attT, g_attT);
    cudaGetSymbolAddress(&p_wq,   g_wq);
    cudaGetSymbolAddress(&p_wp,   g_wp);
    cudaGetSymbolAddress(&p_q,    g_q);
    cudaGetSymbolAddress(&p_k,    g_k);
    cudaGetSymbolAddress(&p_v,    g_v);
    __half* hnT  = (__half*)p_hnT;
    __half* attT = (__half*)p_attT;
    __half* wq   = (__half*)p_wq;
    __half* wp   = (__half*)p_wp;
    __half* gq   = (__half*)p_q;
    __half* gk   = (__half*)p_k;
    __half* gv   = (__half*)p_v;

    static bool attr_set = false;
    if (!attr_set) {
        cudaFuncSetAttribute(attn_f16, cudaFuncAttributeMaxDynamicSharedMemorySize,
                             ATTN_SMEM_BYTES);
        cudaFuncSetAttribute(gemm_f16<0>,
                             cudaFuncAttributeMaxDynamicSharedMemorySize, G_SMEM_BYTES);
        cudaFuncSetAttribute(gemm_f16<1>,
                             cudaFuncAttributeMaxDynamicSharedMemorySize, G_SMEM_BYTES);
        attr_set = true;
    }

    // 0. Weights -> fp16 (single launch)
    {
        int n1 = 3 * Cq * Cq / 4, n2 = Cq * Cq / 4;
        cvt_f16_kernel<<<(n1 + n2 + 255) / 256, 256>>>(w_qkv, wq, n1, w_proj, wp, n2);
    }

    // 1. GroupNorm -> hnT (fp16, transposed)
    gn_kernel<<<Bq * GROUPS, 256>>>(x, gamma, beta, hnT);

    // 2. QKV GEMM -> Q/K [b][h][n][c] (Q scaled), V [b][h][c][n]
    gemm_f16<0><<<dim3(Nq / 128, (3 * Cq) / 128, Bq), 256, G_SMEM_BYTES>>>(
        wq, hnT, b_qkv, nullptr, nullptr, gq, gk, gv, 3 * Cq, Cq, Nq);

    // 3. Flash attention -> attT (128 threads, 32-row warp tiles)
    attn_f16<<<dim3(Nq / 128, HEADS, Bq), 128, ATTN_SMEM_BYTES>>>();

    // 4. Proj GEMM + residual -> f32 out
    gemm_f16<1><<<dim3(Nq / 128, Cq / 128, Bq), 256, G_SMEM_BYTES>>>(
        wp, attT, b_proj, x, out, nullptr, nullptr, nullptr, Cq, Cq, Nq);
}

// round 13
// speedup vs baseline: 1.1093x; 1.0353x over previous
#include <cuda_runtime.h>
#include <cuda_fp16.h>
#include <stdint.h>
#include <math.h>

// Problem constants
#define Bq    8
#define Cq    512
#define Nq    1024
#define HEADS 8
#define HD    64
#define GROUPS 32
#define CPG   16
#define EPS   1e-5f
#define LOG2E 1.4426950408889634f
#define QSC   0.18033688011112042f   // 0.125 * LOG2E
#define ONE2  0x3C003C00u            // fp16 {1.0, 1.0}
#define SC2M8 0x1C001C00u            // fp16 {2^-8, 2^-8}: exact fixed-max shift

// Scratch (device globals — no cudaMalloc allowed)
__device__ __half g_hnT [Bq * Nq * Cq];          // [b][n][c]
__device__ __half g_q   [Bq * HEADS * Nq * HD];  // [b][h][n][c], scale folded
__device__ __half g_k   [Bq * HEADS * Nq * HD];  // [b][h][n][c]
__device__ __half g_v   [Bq * HEADS * HD * Nq];  // [b][h][c][n]
__device__ __half g_attT[Bq * Nq * Cq];          // [b][n][c]
__device__ __half g_wq  [3 * Cq * Cq];
__device__ __half g_wp  [Cq * Cq];

// ---------------------------------------------------------------------------
// helpers
// ---------------------------------------------------------------------------
__device__ __forceinline__ uint32_t ex2h2(uint32_t x) {
    uint32_t r; asm("ex2.approx.f16x2 %0, %1;" : "=r"(r) : "r"(x)); return r;
}
__device__ __forceinline__ uint32_t mulh2(uint32_t a, uint32_t b) {
    uint32_t r; asm("mul.f16x2 %0, %1, %2;" : "=r"(r) : "r"(a), "r"(b)); return r;
}
// pack: lo half <- a, hi half <- b
__device__ __forceinline__ uint32_t packh2(float a, float b) {
    uint32_t r;
    asm("cvt.rn.satfinite.f16x2.f32 %0, %1, %2;" : "=r"(r) : "f"(b), "f"(a));
    return r;
}
// fp16 accumulator MMA: C/D are 2x f16x2 regs
__device__ __forceinline__ void mma_f16acc(uint32_t c[2],
                                           uint32_t a0, uint32_t a1, uint32_t a2, uint32_t a3,
                                           uint32_t b0, uint32_t b1) {
    asm volatile(
        "mma.sync.aligned.m16n8k16.row.col.f16.f16.f16.f16 "
        "{%0,%1}, {%2,%3,%4,%5}, {%6,%7}, {%0,%1};"
        : "+r"(c[0]), "+r"(c[1])
        : "r"(a0), "r"(a1), "r"(a2), "r"(a3), "r"(b0), "r"(b1));
}
__device__ __forceinline__ void ldmx4(uint32_t& r0, uint32_t& r1, uint32_t& r2,
                                      uint32_t& r3, uint32_t addr) {
    asm volatile("ldmatrix.sync.aligned.m8n8.x4.shared.b16 {%0,%1,%2,%3}, [%4];"
                 : "=r"(r0), "=r"(r1), "=r"(r2), "=r"(r3) : "r"(addr));
}
__device__ __forceinline__ uint32_t smem_u32(const void* p) {
    return (uint32_t)__cvta_generic_to_shared(p);
}
__device__ __forceinline__ void cp16s(uint32_t* dst_smem, const void* src) {
    uint32_t d = smem_u32(dst_smem);
    asm volatile("cp.async.cg.shared.global [%0], [%1], 16;" :: "r"(d), "l"(src));
}
__device__ __forceinline__ void cp_commit() {
    asm volatile("cp.async.commit_group;");
}
template <int N>
__device__ __forceinline__ void cp_wait() {
    asm volatile("cp.async.wait_group %0;" :: "n"(N));
}

// ---------------------------------------------------------------------------
// Kernel 1: GroupNorm (blocks 0..255) + weight conversion (blocks 256+),
// merged into one launch so the two memory-bound jobs overlap.
// ---------------------------------------------------------------------------
#define GN_BLOCKS (Bq * GROUPS)          // 256
#define CVT_N1    (3 * Cq * Cq / 4)      // float4 count for w_qkv
#define CVT_N2    (Cq * Cq / 4)
#define CVT_BLOCKS ((CVT_N1 + CVT_N2 + 255) / 256)

__global__ void gn_cvt_kernel(const float* __restrict__ x,
                              const float* __restrict__ gamma,
                              const float* __restrict__ beta,
                              __half* __restrict__ hnT,
                              const float* __restrict__ w1, __half* __restrict__ d1,
                              const float* __restrict__ w2, __half* __restrict__ d2) {
    __shared__ float rs[256], rs2[256];
    __shared__ float ts[256][17];

    const int tid = threadIdx.x;
    if (blockIdx.x >= GN_BLOCKS) {
        // weight conversion path
        int i = (blockIdx.x - GN_BLOCKS) * 256 + tid;
        const float* s; __half* d;
        if (i < CVT_N1) { s = w1; d = d1; }
        else if (i < CVT_N1 + CVT_N2) { s = w2; d = d2; i -= CVT_N1; }
        else return;
        float4 v = ((const float4*)s)[i];
        uint2 u;
        u.x = packh2(v.x, v.y);
        u.y = packh2(v.z, v.w);
        ((uint2*)d)[i] = u;
        return;
    }

    int bg = blockIdx.x;
    int b = bg >> 5, g = bg & 31;
    const size_t base = ((size_t)b * Cq + (size_t)g * CPG) * Nq;
    const float* xp = x + base;

    float s = 0.f, s2 = 0.f;
    for (int i = tid; i < CPG * Nq; i += 256) {
        float v = xp[i];
        s += v; s2 += v * v;
    }
    rs[tid] = s; rs2[tid] = s2;
    __syncthreads();
    for (int st = 128; st > 0; st >>= 1) {
        if (tid < st) { rs[tid] += rs[tid + st]; rs2[tid] += rs2[tid + st]; }
        __syncthreads();
    }
    float mu   = rs[0]  * (1.f / 16384.f);
    float var  = rs2[0] * (1.f / 16384.f) - mu * mu;
    float rinv = rsqrtf(var + EPS);

    const int cl = tid >> 4;
    const int sg = tid & 15;
    const int cg = g * CPG + cl;
    const float ga = gamma[cg] * rinv;
    const float be = beta[cg] - mu * ga;

    __half* hb = hnT + (size_t)b * Nq * Cq;

    for (int chunk = 0; chunk < 4; chunk++) {
        int n0 = chunk * 256;
        const float* src = xp + (size_t)cl * Nq + n0 + sg * 16;
        #pragma unroll
        for (int q = 0; q < 4; q++) {
            float4 v = *(const float4*)(src + q * 4);
            int nl = sg * 16 + q * 4;
            ts[nl + 0][cl] = v.x * ga + be;
            ts[nl + 1][cl] = v.y * ga + be;
            ts[nl + 2][cl] = v.z * ga + be;
            ts[nl + 3][cl] = v.w * ga + be;
        }
        __syncthreads();
        #pragma unroll
        for (int rep = 0; rep < 4; rep++) {
            int nl = (tid >> 2) + rep * 64;
            int j4 = (tid & 3) * 4;
            uint2 u;
            u.x = packh2(ts[nl][j4],     ts[nl][j4 + 1]);
            u.y = packh2(ts[nl][j4 + 2], ts[nl][j4 + 3]);
            *(uint2*)&hb[(size_t)(n0 + nl) * Cq + g * CPG + j4] = u;
        }
        __syncthreads();
    }
}

// ---------------------------------------------------------------------------
// Kernel 2/4: fp16 GEMM, BM=128 BN=128 BK=64, 2-stage, ONE barrier/iter.
// 8 warps (4Mx2N, 32x64/warp), fp16 accumulators, 3 CTAs/SM.
// Row stride 36 u32 (attention-proven conflict-free layout).
// ---------------------------------------------------------------------------
#define GST 4608                         // u32 per stage per operand (128*36)
#define G_SMEM_BYTES (4 * GST * 4)       // 73728

template <int MODE>
__global__ __launch_bounds__(256, 3)
void gemm_f16(const __half* __restrict__ W, const __half* __restrict__ BT,
              const float* __restrict__ bias, const float* __restrict__ resid,
              float* __restrict__ Y,
              __half* __restrict__ gq, __half* __restrict__ gk,
              __half* __restrict__ gv,
              int M, int K, int N) {
    extern __shared__ uint32_t smg[];
    uint32_t* As = smg;
    uint32_t* Bs = smg + 2 * GST;

    const int b  = blockIdx.z;
    const int m0 = blockIdx.y * 128, n0 = blockIdx.x * 128;
    const __half* BTb = BT + (size_t)b * Nq * Cq;

    const int tid  = threadIdx.x;
    const int lane = tid & 31, warp = tid >> 5;
    const int g = lane >> 2, t = lane & 3;
    const int wm = (warp >> 1) * 32;
    const int wn = (warp & 1) * 64;

    const int a_row  = lane & 15;
    const int a_coff = ((lane >> 4) & 1) * 4;
    const int b_row  = (lane & 7) + ((lane >> 4) & 1) * 8;
    const int b_coff = ((lane >> 3) & 1) * 4;

    // fp16 accumulators: acc[mt][nt][0] = row g cols (2t,2t+1); [1] = row g+8
    uint32_t acc[2][8][2];
    #pragma unroll
    for (int i = 0; i < 2; i++)
        #pragma unroll
        for (int j = 0; j < 8; j++) { acc[i][j][0] = 0u; acc[i][j][1] = 0u; }

    const int NIT = K / 64;   // 8

    auto load_stage = [&](int stage, int k0) {
        uint32_t* as = As + stage * GST;
        uint32_t* bs = Bs + stage * GST;
        #pragma unroll
        for (int r = 0; r < 4; r++) {
            int idx = tid + r * 256;      // 0..1023
            int row = idx >> 3, ch = idx & 7;
            cp16s(as + row * 36 + ch * 4, W   + (size_t)(m0 + row) * K + k0 + ch * 8);
            cp16s(bs + row * 36 + ch * 4, BTb + (size_t)(n0 + row) * K + k0 + ch * 8);
        }
    };

    load_stage(0, 0);
    cp_commit();

    for (int it = 0; it < NIT; it++) {
        cp_wait<0>();
        __syncthreads();
        if (it + 1 < NIT) {
            load_stage((it + 1) & 1, (it + 1) * 64);
            cp_commit();
        }

        uint32_t asb = smem_u32(As + (it & 1) * GST);
        uint32_t bsb = smem_u32(Bs + (it & 1) * GST);
        #pragma unroll
        for (int s = 0; s < 4; s++) {
            uint32_t af[2][4];
            #pragma unroll
            for (int mt = 0; mt < 2; mt++)
                ldmx4(af[mt][0], af[mt][1], af[mt][2], af[mt][3],
                      asb + ((wm + mt * 16 + a_row) * 36 + 8 * s + a_coff) * 4);
            uint32_t bb[16];
            #pragma unroll
            for (int p = 0; p < 4; p++)
                ldmx4(bb[4 * p], bb[4 * p + 1], bb[4 * p + 2], bb[4 * p + 3],
                      bsb + ((wn + p * 16 + b_row) * 36 + 8 * s + b_coff) * 4);
            #pragma unroll
            for (int nt = 0; nt < 8; nt++) {
                uint32_t b0 = bb[4 * (nt >> 1) + 2 * (nt & 1)];
                uint32_t b1 = bb[4 * (nt >> 1) + 2 * (nt & 1) + 1];
                mma_f16acc(acc[0][nt], af[0][0], af[0][1], af[0][2], af[0][3], b0, b1);
                mma_f16acc(acc[1][nt], af[1][0], af[1][1], af[1][2], af[1][3], b0, b1);
            }
        }
    }

    if (MODE == 0) {
        const int sel = m0 >> 9;
        #pragma unroll
        for (int mt = 0; mt < 2; mt++) {
            int m  = m0 + wm + mt * 16 + g;
            float bv0 = bias[m], bv1 = bias[m + 8];
            int hh = (m >> 6) & 7;
            int c0 = m & 63;
            #pragma unroll
            for (int nt = 0; nt < 8; nt++) {
                int n = n0 + wn + nt * 8 + 2 * t;
                __half2 h0 = *(__half2*)&acc[mt][nt][0];
                __half2 h1 = *(__half2*)&acc[mt][nt][1];
                float v00 = __low2float(h0) + bv0, v01 = __high2float(h0) + bv0;
                float v10 = __low2float(h1) + bv1, v11 = __high2float(h1) + bv1;
                if (sel == 0) {
                    size_t qb = ((size_t)(b * 8 + hh) * 1024);
                    gq[(qb + n) * 64 + c0]         = __float2half_rn(v00 * QSC);
                    gq[(qb + n + 1) * 64 + c0]     = __float2half_rn(v01 * QSC);
                    gq[(qb + n) * 64 + c0 + 8]     = __float2half_rn(v10 * QSC);
                    gq[(qb + n + 1) * 64 + c0 + 8] = __float2half_rn(v11 * QSC);
                } else if (sel == 1) {
                    size_t kb = ((size_t)(b * 8 + hh) * 1024);
                    gk[(kb + n) * 64 + c0]         = __float2half_rn(v00);
                    gk[(kb + n + 1) * 64 + c0]     = __float2half_rn(v01);
                    gk[(kb + n) * 64 + c0 + 8]     = __float2half_rn(v10);
                    gk[(kb + n + 1) * 64 + c0 + 8] = __float2half_rn(v11);
                } else {
                    size_t vb = ((size_t)(b * 8 + hh) * 64);
                    *(uint32_t*)&gv[(vb + c0) * 1024 + n]     = packh2(v00, v01);
                    *(uint32_t*)&gv[(vb + c0 + 8) * 1024 + n] = packh2(v10, v11);
                }
            }
        }
    } else {
        float*       Yb = Y + (size_t)b * Cq * Nq;
        const float* Rb = resid + (size_t)b * Cq * Nq;
        #pragma unroll
        for (int mt = 0; mt < 2; mt++) {
            int r0 = m0 + wm + mt * 16 + g;
            int r1 = r0 + 8;
            float bv0 = bias[r0], bv1 = bias[r1];
            #pragma unroll
            for (int nt = 0; nt < 8; nt++) {
                int cc = n0 + wn + nt * 8 + 2 * t;
                __half2 h0 = *(__half2*)&acc[mt][nt][0];
                __half2 h1 = *(__half2*)&acc[mt][nt][1];
                float2 q0 = *(const float2*)&Rb[(size_t)r0 * N + cc];
                float2 q1 = *(const float2*)&Rb[(size_t)r1 * N + cc];
                float2 v0 = make_float2(__low2float(h0) + bv0 + q0.x,
                                        __high2float(h0) + bv0 + q0.y);
                float2 v1 = make_float2(__low2float(h1) + bv1 + q1.x,
                                        __high2float(h1) + bv1 + q1.y);
                *(float2*)&Yb[(size_t)r0 * N + cc] = v0;
                *(float2*)&Yb[(size_t)r1 * N + cc] = v1;
            }
        }
    }
}

// ---------------------------------------------------------------------------
// Kernel 3: fp16 flash attention, 128 threads / 4 warps, 32-row warp tiles.
// ONE barrier per kt iteration (prefetch moved after the barrier).
// ---------------------------------------------------------------------------
#define AK_OFF  4608
#define AK_STG  2304          // 64*36
#define AV_OFF  9216
#define AV_STG  2304
#define ATTN_SMEM_BYTES (13824 * 4)

__global__ __launch_bounds__(128, 4)
void attn_f16() {
    extern __shared__ uint32_t sma[];
    uint32_t* Qs = sma;
    uint32_t* Ks = sma + AK_OFF;
    uint32_t* Vs = sma + AV_OFF;

    const int qt = blockIdx.x, h = blockIdx.y, b = blockIdx.z;
    const __half* Qp = g_q + ((size_t)(b * 8 + h) * 1024 + qt * 128) * 64;
    const __half* Kp = g_k + ((size_t)(b * 8 + h) * 1024) * 64;
    const __half* Vp = g_v + ((size_t)(b * 8 + h) * 64) * 1024;

    const int tid = threadIdx.x, lane = tid & 31, w = tid >> 5;
    const int g = lane >> 2, t = lane & 3;

    const int b_row  = (lane & 7) + ((lane >> 4) & 1) * 8;
    const int b_coff = ((lane >> 3) & 1) * 4;

    // prefetch K/V tile 0 + Q tile
    #pragma unroll
    for (int r = 0; r < 4; r++) {
        int idx = tid + r * 128;
        int row = idx >> 3, ch = idx & 7;
        cp16s(Ks + row * 36 + ch * 4, Kp + (size_t)row * 64 + ch * 8);
        cp16s(Vs + row * 36 + ch * 4, Vp + (size_t)row * 1024 + ch * 8);
    }
    cp_commit();
    #pragma unroll
    for (int r = 0; r < 8; r++) {
        int idx = tid + r * 128;
        int row = idx >> 3, ch = idx & 7;
        cp16s(Qs + row * 36 + ch * 4, Qp + (size_t)row * 64 + ch * 8);
    }
    cp_commit();
    cp_wait<0>();
    __syncthreads();

    // Q fragments: 2 m16 tiles x 4 k-steps
    uint32_t qf[2][4][4];
    #pragma unroll
    for (int mt = 0; mt < 2; mt++) {
        const int ib = w * 32 + mt * 16;
        #pragma unroll
        for (int s = 0; s < 4; s++) {
            qf[mt][s][0] = Qs[(ib + g) * 36 + t + 8 * s];
            qf[mt][s][1] = Qs[(ib + g + 8) * 36 + t + 8 * s];
            qf[mt][s][2] = Qs[(ib + g) * 36 + t + 4 + 8 * s];
            qf[mt][s][3] = Qs[(ib + g + 8) * 36 + t + 4 + 8 * s];
        }
    }

    // O and l as fp16 C-fragments, per m-tile
    uint32_t of[2][8][2];
    #pragma unroll
    for (int mt = 0; mt < 2; mt++)
        #pragma unroll
        for (int i = 0; i < 8; i++) { of[mt][i][0] = 0u; of[mt][i][1] = 0u; }
    uint32_t lacc[2][2] = {{0u, 0u}, {0u, 0u}};

    for (int kt = 0; kt < 16; kt++) {
        if (kt > 0) {
            cp_wait<0>();      // tile kt resident
            __syncthreads();   // all warps done computing on buf (kt-1)&1
        }
        if (kt + 1 < 16) {     // prefetch kt+1 into buf (kt+1)&1 (== (kt-1)&1)
            int ps = (kt + 1) & 1, j0 = (kt + 1) * 64;
            uint32_t* ks = Ks + ps * AK_STG;
            uint32_t* vs = Vs + ps * AV_STG;
            #pragma unroll
            for (int r = 0; r < 4; r++) {
                int idx = tid + r * 128;
                int row = idx >> 3, ch = idx & 7;
                cp16s(ks + row * 36 + ch * 4, Kp + (size_t)(j0 + row) * 64 + ch * 8);
                cp16s(vs + row * 36 + ch * 4, Vp + (size_t)row * 1024 + j0 + ch * 8);
            }
            cp_commit();
        }

        uint32_t ksb = smem_u32(Ks + (kt & 1) * AK_STG);
        uint32_t vsb = smem_u32(Vs + (kt & 1) * AV_STG);

        // S = Q K^T in fp16 C-frags, both m-tiles share kb fragments
        uint32_t sc[2][8][2];
        #pragma unroll
        for (int mt = 0; mt < 2; mt++)
            #pragma unroll
            for (int i = 0; i < 8; i++) { sc[mt][i][0] = 0u; sc[mt][i][1] = 0u; }
        #pragma unroll
        for (int s = 0; s < 4; s++) {
            uint32_t kb[16];
            #pragma unroll
            for (int p = 0; p < 4; p++)
                ldmx4(kb[4 * p], kb[4 * p + 1], kb[4 * p + 2], kb[4 * p + 3],
                      ksb + ((p * 16 + b_row) * 36 + 8 * s + b_coff) * 4);
            #pragma unroll
            for (int nt = 0; nt < 8; nt++) {
                uint32_t b0 = kb[4 * (nt >> 1) + 2 * (nt & 1)];
                uint32_t b1 = kb[4 * (nt >> 1) + 2 * (nt & 1) + 1];
                mma_f16acc(sc[0][nt], qf[0][s][0], qf[0][s][1], qf[0][s][2], qf[0][s][3], b0, b1);
                mma_f16acc(sc[1][nt], qf[1][s][0], qf[1][s][1], qf[1][s][2], qf[1][s][3], b0, b1);
            }
        }

        // O += P V^T ; l += P @ ones ; p = ex2(s) * 2^-8, vb shared across mt
        #pragma unroll
        for (int s = 0; s < 4; s++) {
            uint32_t vb[16];
            #pragma unroll
            for (int p = 0; p < 4; p++)
                ldmx4(vb[4 * p], vb[4 * p + 1], vb[4 * p + 2], vb[4 * p + 3],
                      vsb + ((p * 16 + b_row) * 36 + 8 * s + b_coff) * 4);
            #pragma unroll
            for (int mt = 0; mt < 2; mt++) {
                uint32_t a0 = mulh2(ex2h2(sc[mt][2 * s][0]),     SC2M8);
                uint32_t a1 = mulh2(ex2h2(sc[mt][2 * s][1]),     SC2M8);
                uint32_t a2 = mulh2(ex2h2(sc[mt][2 * s + 1][0]), SC2M8);
                uint32_t a3 = mulh2(ex2h2(sc[mt][2 * s + 1][1]), SC2M8);
                #pragma unroll
                for (int ct = 0; ct < 8; ct++) {
                    uint32_t b0 = vb[4 * (ct >> 1) + 2 * (ct & 1)];
                    uint32_t b1 = vb[4 * (ct >> 1) + 2 * (ct & 1) + 1];
                    mma_f16acc(of[mt][ct], a0, a1, a2, a3, b0, b1);
                }
                mma_f16acc(lacc[mt], a0, a1, a2, a3, ONE2, ONE2);
            }
        }
    }

    // normalize + store attT[b][n][c]
    __half* ob = g_attT + (size_t)b * Nq * Cq + h * 64;
    #pragma unroll
    for (int mt = 0; mt < 2; mt++) {
        float inv0 = 1.f / __low2float(*(__half2*)&lacc[mt][0]);
        float inv1 = 1.f / __low2float(*(__half2*)&lacc[mt][1]);
        int n0i = qt * 128 + w * 32 + mt * 16 + g;
        #pragma unroll
        for (int ct = 0; ct < 8; ct++) {
            int cch = ct * 8 + 2 * t;
            __half2 p0 = *(__half2*)&of[mt][ct][0];
            __half2 p1 = *(__half2*)&of[mt][ct][1];
            *(uint32_t*)&ob[(size_t)n0i * Cq + cch] =
                packh2(__low2float(p0) * inv0, __high2float(p0) * inv0);
            *(uint32_t*)&ob[(size_t)(n0i + 8) * Cq + cch] =
                packh2(__low2float(p1) * inv1, __high2float(p1) * inv1);
        }
    }
}

// ---------------------------------------------------------------------------
extern "C" void kernel_launch(void* const* d_in, const int* in_sizes, int n_in,
                              void* d_out, int out_size) {
    const float* x      = (const float*)d_in[0];
    const float* gamma  = (const float*)d_in[1];
    const float* beta   = (const float*)d_in[2];
    const float* w_qkv  = (const float*)d_in[3];
    const float* b_qkv  = (const float*)d_in[4];
    const float* w_proj = (const float*)d_in[5];
    const float* b_proj = (const float*)d_in[6];
    float* out = (float*)d_out;

    void *p_hnT, *p_attT, *p_wq, *p_wp, *p_q, *p_k, *p_v;
    cudaGetSymbolAddress(&p_hnT,  g_hnT);
    cudaGetSymbolAddress(&p_attT, g_attT);
    cudaGetSymbolAddress(&p_wq,   g_wq);
    cudaGetSymbolAddress(&p_wp,   g_wp);
    cudaGetSymbolAddress(&p_q,    g_q);
    cudaGetSymbolAddress(&p_k,    g_k);
    cudaGetSymbolAddress(&p_v,    g_v);
    __half* hnT  = (__half*)p_hnT;
    __half* attT = (__half*)p_attT;
    __half* wq   = (__half*)p_wq;
    __half* wp   = (__half*)p_wp;
    __half* gq   = (__half*)p_q;
    __half* gk   = (__half*)p_k;
    __half* gv   = (__half*)p_v;

    static bool attr_set = false;
    if (!attr_set) {
        cudaFuncSetAttribute(attn_f16, cudaFuncAttributeMaxDynamicSharedMemorySize,
                             ATTN_SMEM_BYTES);
        cudaFuncSetAttribute(gemm_f16<0>,
                             cudaFuncAttributeMaxDynamicSharedMemorySize, G_SMEM_BYTES);
        cudaFuncSetAttribute(gemm_f16<1>,
                             cudaFuncAttributeMaxDynamicSharedMemorySize, G_SMEM_BYTES);
        attr_set = true;
    }

    // 1. GroupNorm -> hnT + weight conversion (merged, overlapping)
    gn_cvt_kernel<<<GN_BLOCKS + CVT_BLOCKS, 256>>>(
        x, gamma, beta, hnT, w_qkv, wq, w_proj, wp);

    // 2. QKV GEMM -> Q/K [b][h][n][c] (Q scaled), V [b][h][c][n]
    gemm_f16<0><<<dim3(Nq / 128, (3 * Cq) / 128, Bq), 256, G_SMEM_BYTES>>>(
        wq, hnT, b_qkv, nullptr, nullptr, gq, gk, gv, 3 * Cq, Cq, Nq);

    // 3. Flash attention -> attT (128 threads, 32-row warp tiles)
    attn_f16<<<dim3(Nq / 128, HEADS, Bq), 128, ATTN_SMEM_BYTES>>>();

    // 4. Proj GEMM + residual -> f32 out
    gemm_f16<1><<<dim3(Nq / 128, Cq / 128, Bq), 256, G_SMEM_BYTES>>>(
        wp, attT, b_proj, x, out, nullptr, nullptr, nullptr, Cq, Cq, Nq);
}